// round 10
// baseline (speedup 1.0000x reference)
#include <cuda_runtime.h>
#include <cuda_bf16.h>
#include <cuda_fp16.h>

#define BB 2
#define SS 2048
#define DIM 1024
#define HH 16
#define HD 64
#define BSD (BB*SS*DIM)
#define DD  (DIM*DIM)

// ---------------- scratch ----------------
__device__ unsigned g_absmax[8];
__device__ float g_scales[8];
__device__ __align__(256) __nv_bfloat16 g_Xq[BSD];
__device__ __align__(256) __nv_bfloat16 g_Aq[BSD];
__device__ __align__(256) __nv_bfloat16 g_Wb[4][DD];
__device__ __align__(256) float g_Q[BSD];
__device__ __align__(256) __half g_Khi[BSD];   // [token][d] fp16 hi
__device__ __align__(256) __half g_Klo[BSD];   // [token][d] fp16 lo
__device__ __align__(256) __half g_VThi[BSD];  // [b,h][d][token] fp16 hi (transposed)
__device__ __align__(256) __half g_VTlo[BSD];
__device__ __align__(256) float g_attn[BSD];

// ---------------- helpers ----------------
__device__ __forceinline__ void cpasync16(unsigned saddr, const void* g) {
    asm volatile("cp.async.cg.shared.global [%0], [%1], 16;" :: "r"(saddr), "l"(g));
}
#define CP_COMMIT asm volatile("cp.async.commit_group;")
#define CP_WAIT(n) asm volatile("cp.async.wait_group %0;" :: "n"(n))

__device__ __forceinline__ void ldmat4(unsigned* r, unsigned addr) {
    asm volatile("ldmatrix.sync.aligned.m8n8.x4.shared.b16 {%0,%1,%2,%3},[%4];"
        : "=r"(r[0]), "=r"(r[1]), "=r"(r[2]), "=r"(r[3]) : "r"(addr));
}
__device__ __forceinline__ void mma16816(float* c, const unsigned* a, const unsigned* b) {
    asm volatile("mma.sync.aligned.m16n8k16.row.col.f32.bf16.bf16.f32 "
        "{%0,%1,%2,%3},{%4,%5,%6,%7},{%8,%9},{%0,%1,%2,%3};"
        : "+f"(c[0]), "+f"(c[1]), "+f"(c[2]), "+f"(c[3])
        : "r"(a[0]), "r"(a[1]), "r"(a[2]), "r"(a[3]), "r"(b[0]), "r"(b[1]));
}
// fp16 MMA, fp32 accumulate
#define MMAH(c, a, b0, b1) \
  asm volatile("mma.sync.aligned.m16n8k16.row.col.f32.f16.f16.f32 " \
    "{%0,%1,%2,%3},{%4,%5,%6,%7},{%8,%9},{%0,%1,%2,%3};" \
    : "+f"(c[0]), "+f"(c[1]), "+f"(c[2]), "+f"(c[3]) \
    : "r"(a[0]), "r"(a[1]), "r"(a[2]), "r"(a[3]), "r"(b0), "r"(b1))

// split (x,y) into packed fp16 hi/lo half2 pairs (Dekker)
__device__ __forceinline__ unsigned sp_split(float x, float y, unsigned& lo) {
    __half hx = __float2half_rn(x), hy = __float2half_rn(y);
    __half lx = __float2half_rn(x - __half2float(hx));
    __half ly = __float2half_rn(y - __half2float(hy));
    __half2 H = __halves2half2(hx, hy), L = __halves2half2(lx, ly);
    lo = *(unsigned*)&L;
    return *(unsigned*)&H;
}

// ---------------- batched absmax ----------------
__global__ void absmax_all_k(const float* __restrict__ h,
                             const float* w0, const float* w1,
                             const float* w2, const float* w3) {
    int y = blockIdx.y;
    const float* x = y == 0 ? h : y == 1 ? w0 : y == 2 ? w1 : y == 3 ? w2 : w3;
    int n4 = (y == 0 ? BSD : DD) >> 2;
    const float4* x4 = (const float4*)x;
    float m = 0.f;
    int stride = gridDim.x * blockDim.x;
    for (int i = blockIdx.x * blockDim.x + threadIdx.x; i < n4; i += stride) {
        float4 v = x4[i];
        m = fmaxf(m, fmaxf(fmaxf(fabsf(v.x), fabsf(v.y)), fmaxf(fabsf(v.z), fabsf(v.w))));
    }
    #pragma unroll
    for (int o = 16; o; o >>= 1) m = fmaxf(m, __shfl_xor_sync(0xffffffffu, m, o));
    __shared__ float sm[8];
    if ((threadIdx.x & 31) == 0) sm[threadIdx.x >> 5] = m;
    __syncthreads();
    if (threadIdx.x < 32) {
        m = (threadIdx.x < 8u) ? sm[threadIdx.x] : 0.f;
        #pragma unroll
        for (int o = 4; o; o >>= 1) m = fmaxf(m, __shfl_xor_sync(0xffffffffu, m, o));
        if (threadIdx.x == 0) atomicMax(&g_absmax[y], __float_as_uint(m));
    }
}

// ---------------- batched quantize ----------------
__global__ void quant_all_k(const float* __restrict__ h,
                            const float* w0, const float* w1,
                            const float* w2, const float* w3) {
    int y = blockIdx.y;
    const float* x = y == 0 ? h : y == 1 ? w0 : y == 2 ? w1 : y == 3 ? w2 : w3;
    __nv_bfloat16* out = y == 0 ? g_Xq : g_Wb[y - 1];
    int n4 = (y == 0 ? BSD : DD) >> 2;
    float s = fmaxf(__fdiv_rn(__uint_as_float(g_absmax[y]), 127.0f), 1e-8f);
    if (blockIdx.x == 0 && threadIdx.x == 0) g_scales[y] = s;
    int stride = gridDim.x * blockDim.x;
    for (int i = blockIdx.x * blockDim.x + threadIdx.x; i < n4; i += stride) {
        float4 v = ((const float4*)x)[i];
        __nv_bfloat162 lo = __floats2bfloat162_rn(rintf(__fdiv_rn(v.x, s)), rintf(__fdiv_rn(v.y, s)));
        __nv_bfloat162 hi = __floats2bfloat162_rn(rintf(__fdiv_rn(v.z, s)), rintf(__fdiv_rn(v.w, s)));
        uint2 pack;
        pack.x = *(unsigned*)&lo;
        pack.y = *(unsigned*)&hi;
        ((uint2*)out)[i] = pack;
    }
}

// ---------------- attn quantize ----------------
__global__ void quant_attn_k() {
    float s = fmaxf(__fdiv_rn(__uint_as_float(g_absmax[5]), 127.0f), 1e-8f);
    if (blockIdx.x == 0 && threadIdx.x == 0) g_scales[5] = s;
    int stride = gridDim.x * blockDim.x;
    for (int i = blockIdx.x * blockDim.x + threadIdx.x; i < (BSD >> 2); i += stride) {
        float4 v = ((const float4*)g_attn)[i];
        __nv_bfloat162 lo = __floats2bfloat162_rn(rintf(__fdiv_rn(v.x, s)), rintf(__fdiv_rn(v.y, s)));
        __nv_bfloat162 hi = __floats2bfloat162_rn(rintf(__fdiv_rn(v.z, s)), rintf(__fdiv_rn(v.w, s)));
        uint2 pack;
        pack.x = *(unsigned*)&lo;
        pack.y = *(unsigned*)&hi;
        ((uint2*)g_Aq)[i] = pack;
    }
}

// ================= pipelined bf16 GEMM core (unchanged) =================
#define BM2 128
#define BN2 64
#define BK2 32
#define PKB 80
#define STG_BYTES ((BM2 + BN2) * PKB)
#define KTILES (DIM / BK2)

__device__ __forceinline__ void gemm_body(const __nv_bfloat16* __restrict__ A,
                                          const __nv_bfloat16* __restrict__ B,
                                          const float* __restrict__ bias,
                                          float* __restrict__ cext, int c_sel,
                                          float scale, char* sm2) {
    const int rb = blockIdx.y * BM2, cb = blockIdx.x * BN2;
    const int tid = threadIdx.x, wid = tid >> 5, lane = tid & 31;
    const unsigned sbase = (unsigned)__cvta_generic_to_shared(sm2);

    const int wm = wid & 3, wn = wid >> 2;
    const int a_row = wm * 32 + (lane & 7) + ((lane >> 3) & 1) * 8;
    const int a_koff = (lane >> 4) * 8;
    const int b_row = wn * 32 + (lane & 7) + (lane >> 4) * 8;
    const int b_koff = ((lane >> 3) & 1) * 8;

    float c[2][4][4];
    #pragma unroll
    for (int mt = 0; mt < 2; mt++)
        #pragma unroll
        for (int nt = 0; nt < 4; nt++)
            #pragma unroll
            for (int e = 0; e < 4; e++) c[mt][nt][e] = 0.f;

    auto issue = [&](int ki) {
        int kt = ki * BK2;
        unsigned s = sbase + (ki % 3) * STG_BYTES;
        #pragma unroll
        for (int r2 = 0; r2 < 2; r2++) {
            int cidx = tid + r2 * 256;
            int row = cidx >> 2, ch = cidx & 3;
            cpasync16(s + row * PKB + ch * 16, A + (size_t)(rb + row) * DIM + kt + ch * 8);
        }
        {
            int row = tid >> 2, ch = tid & 3;
            cpasync16(s + BM2 * PKB + row * PKB + ch * 16, B + (size_t)(cb + row) * DIM + kt + ch * 8);
        }
        CP_COMMIT;
    };

    issue(0);
    issue(1);

    for (int i = 0; i < KTILES; i++) {
        if (i + 1 < KTILES) { CP_WAIT(1); } else { CP_WAIT(0); }
        __syncthreads();
        if (i + 2 < KTILES) issue(i + 2);
        unsigned s = sbase + (i % 3) * STG_BYTES;
        #pragma unroll
        for (int ks = 0; ks < BK2; ks += 16) {
            unsigned af[2][4], bf[2][4];
            ldmat4(af[0], s + a_row * PKB + (ks + a_koff) * 2);
            ldmat4(af[1], s + (a_row + 16) * PKB + (ks + a_koff) * 2);
            ldmat4(bf[0], s + BM2 * PKB + b_row * PKB + (ks + b_koff) * 2);
            ldmat4(bf[1], s + BM2 * PKB + (b_row + 16) * PKB + (ks + b_koff) * 2);
            #pragma unroll
            for (int mt = 0; mt < 2; mt++)
                #pragma unroll
                for (int nt = 0; nt < 4; nt++)
                    mma16816(c[mt][nt], af[mt], &bf[nt >> 1][(nt & 1) * 2]);
        }
        __syncthreads();
    }

    const int g = lane >> 2, tig = lane & 3;
    #pragma unroll
    for (int mt = 0; mt < 2; mt++) {
        #pragma unroll
        for (int nt = 0; nt < 4; nt++) {
            int col = cb + wn * 32 + nt * 8 + 2 * tig;
            float2 bv = *(const float2*)&bias[col];
            #pragma unroll
            for (int half = 0; half < 2; half++) {
                int row = rb + wm * 32 + mt * 16 + g + half * 8;
                float x = c[mt][nt][half * 2]     * scale + bv.x;
                float y = c[mt][nt][half * 2 + 1] * scale + bv.y;
                size_t off = (size_t)row * DIM + col;
                if (c_sel == 0) {
                    *(float2*)&g_Q[off] = make_float2(x, y);
                } else if (c_sel == 1) {
                    unsigned lo, hi = sp_split(x, y, lo);
                    *(unsigned*)&g_Khi[off] = hi;
                    *(unsigned*)&g_Klo[off] = lo;
                } else if (c_sel == 2) {
                    __half hx = __float2half_rn(x), hy = __float2half_rn(y);
                    __half lx = __float2half_rn(x - __half2float(hx));
                    __half ly = __float2half_rn(y - __half2float(hy));
                    int brow = row >> 11, tok = row & (SS - 1);
                    int hh = col >> 6, dd = col & 63;
                    size_t offT = ((size_t)((brow * HH + hh) * HD + dd)) * SS + tok;
                    g_VThi[offT] = hx;      g_VTlo[offT] = lx;
                    g_VThi[offT + SS] = hy; g_VTlo[offT + SS] = ly;
                } else {
                    *(float2*)&cext[off] = make_float2(x, y);
                }
            }
        }
    }
}

__global__ void __launch_bounds__(256) gemm_qkv_k(const float* __restrict__ bq,
                                                  const float* __restrict__ bk,
                                                  const float* __restrict__ bv) {
    extern __shared__ char sm2[];
    int z = blockIdx.z;
    const float* bias = z == 0 ? bq : z == 1 ? bk : bv;
    float scale = g_scales[0] * g_scales[1 + z];
    gemm_body(g_Xq, g_Wb[z], bias, nullptr, z, scale, sm2);
}

__global__ void __launch_bounds__(256) gemm_o_k(const float* __restrict__ bo,
                                                float* __restrict__ out) {
    extern __shared__ char sm2[];
    float scale = g_scales[5] * g_scales[4];
    gemm_body(g_Aq, g_Wb[3], bo, out, 3, scale, sm2);
}

// ================= fp16 3-term flash attention, reg-resident P, LDSM =================
// BQ=128 (8 warps x 16 q-rows), BK=64, double-buffered K/V, 256 threads, 2 CTAs/SM.
// K smem:  [64 keys][128B dims]   (hi and lo planes)
// V smem:  [64 dims][128B keys]   (hi and lo planes, from transposed V)
// Plain 128B rows; all B-operands fetched with ldmatrix.x4 (row reads: conflict-free).

#define AB_KH 0          /* 2 bufs x 8192 */
#define AB_KL 16384
#define AB_VH 32768
#define AB_VL 49152
#define AB_MS 65536      /* 2 x 256B mask */
#define AB_SRED 66048
#define AB_SMEM 66080

__global__ void __launch_bounds__(256, 2) attn_k(const float* __restrict__ mask) {
    extern __shared__ char smc[];
    const unsigned sb = (unsigned)__cvta_generic_to_shared(smc);

    const int b = blockIdx.z, h = blockIdx.y;
    const int q0 = blockIdx.x * 128;
    const int tid = threadIdx.x;
    const int wid = tid >> 5, lane = tid & 31;
    const int g = lane >> 2, tig = lane & 3;
    const size_t base = (size_t)b * SS * DIM + (size_t)h * HD;
    const size_t baseT = (size_t)(b * HH + h) * HD * SS;

    // ldmatrix lane offset: matrix row (lane&7), matrix index (lane>>3) along dims
    const unsigned laneoff = (lane & 7) * 128 + (lane >> 3) * 16;

    // ---- Q fragments straight from gmem (hi/lo fp16, 0.125 folded) ----
    unsigned qh[4][4], ql[4][4];
    {
        const float* Qr0 = &g_Q[base + (size_t)(q0 + wid * 16 + g) * DIM];
        const float* Qr8 = Qr0 + 8 * DIM;
        #pragma unroll
        for (int kg = 0; kg < 4; kg++) {
            float2 v0 = *(const float2*)&Qr0[kg * 16 + 2 * tig];
            float2 v1 = *(const float2*)&Qr8[kg * 16 + 2 * tig];
            float2 v2 = *(const float2*)&Qr0[kg * 16 + 2 * tig + 8];
            float2 v3 = *(const float2*)&Qr8[kg * 16 + 2 * tig + 8];
            qh[kg][0] = sp_split(v0.x * 0.125f, v0.y * 0.125f, ql[kg][0]);
            qh[kg][1] = sp_split(v1.x * 0.125f, v1.y * 0.125f, ql[kg][1]);
            qh[kg][2] = sp_split(v2.x * 0.125f, v2.y * 0.125f, ql[kg][2]);
            qh[kg][3] = sp_split(v3.x * 0.125f, v3.y * 0.125f, ql[kg][3]);
        }
    }

    // tile loader: 4 planes x 64 rows x 128B, one commit group
    auto issue_tile = [&](int kt, int buf) {
        const char* gKh = (const char*)&g_Khi[base + (size_t)kt * DIM];
        const char* gKl = (const char*)&g_Klo[base + (size_t)kt * DIM];
        const char* gVh = (const char*)g_VThi + 2 * (baseT + kt);
        const char* gVl = (const char*)g_VTlo + 2 * (baseT + kt);
        unsigned o = buf * 8192;
        #pragma unroll
        for (int c = 0; c < 2; c++) {
            int idx = tid + c * 256;
            int r = idx >> 3, ch = idx & 7;
            unsigned so = r * 128 + ch * 16;
            cpasync16(sb + AB_KH + o + so, gKh + (size_t)r * (DIM * 2) + ch * 16);
            cpasync16(sb + AB_KL + o + so, gKl + (size_t)r * (DIM * 2) + ch * 16);
            cpasync16(sb + AB_VH + o + so, gVh + (size_t)r * (SS * 2) + ch * 16);
            cpasync16(sb + AB_VL + o + so, gVl + (size_t)r * (SS * 2) + ch * 16);
        }
        if (tid < 16)
            cpasync16(sb + AB_MS + buf * 256 + tid * 16,
                      (const char*)&mask[(size_t)b * SS + kt] + tid * 16);
        CP_COMMIT;
    };

    issue_tile(0, 0);

    float m0 = -1e30f, m8 = -1e30f, l0 = 0.f, l8 = 0.f;
    float o[8][4];
    #pragma unroll
    for (int n = 0; n < 8; n++)
        #pragma unroll
        for (int e = 0; e < 4; e++) o[n][e] = 0.f;

    for (int it = 0; it < SS / 64; it++) {
        const int cur = it & 1;
        CP_WAIT(0);
        __syncthreads();     // buffer cur ready; all warps done with buffer 1-cur
        if (it + 1 < SS / 64) issue_tile((it + 1) * 64, 1 - cur);

        const unsigned sK = sb + cur * 8192;
        const unsigned sV = sb + cur * 8192;
        const float* Mc = (const float*)(smc + AB_MS + cur * 256);

        // ---- S = (Q/8) K^T : B via ldmatrix.x4 ----
        float s[8][4];
        #pragma unroll
        for (int n = 0; n < 8; n++)
            #pragma unroll
            for (int e = 0; e < 4; e++) s[n][e] = 0.f;

        #pragma unroll
        for (int n = 0; n < 8; n++) {
            unsigned bh[8], bl[8];
            ldmat4(bh,     sK + AB_KH + n * 1024 + laneoff);        // kg0,1
            ldmat4(bh + 4, sK + AB_KH + n * 1024 + 64 + laneoff);   // kg2,3
            ldmat4(bl,     sK + AB_KL + n * 1024 + laneoff);
            ldmat4(bl + 4, sK + AB_KL + n * 1024 + 64 + laneoff);
            #pragma unroll
            for (int kg = 0; kg < 4; kg++) {
                MMAH(s[n], qh[kg], bh[kg * 2], bh[kg * 2 + 1]);
                MMAH(s[n], ql[kg], bh[kg * 2], bh[kg * 2 + 1]);
                MMAH(s[n], qh[kg], bl[kg * 2], bl[kg * 2 + 1]);
            }
        }

        // ---- online softmax (rows g / g+8) ----
        float mx0 = -1e30f, mx8 = -1e30f;
        #pragma unroll
        for (int n = 0; n < 8; n++) {
            float2 mm = *(const float2*)&Mc[n * 8 + 2 * tig];
            float bx = mm.x * 10000.0f - 10000.0f;
            float by = mm.y * 10000.0f - 10000.0f;
            s[n][0] += bx; s[n][1] += by;
            s[n][2] += bx; s[n][3] += by;
            mx0 = fmaxf(mx0, fmaxf(s[n][0], s[n][1]));
            mx8 = fmaxf(mx8, fmaxf(s[n][2], s[n][3]));
        }
        mx0 = fmaxf(mx0, __shfl_xor_sync(0xffffffffu, mx0, 1));
        mx0 = fmaxf(mx0, __shfl_xor_sync(0xffffffffu, mx0, 2));
        mx8 = fmaxf(mx8, __shfl_xor_sync(0xffffffffu, mx8, 1));
        mx8 = fmaxf(mx8, __shfl_xor_sync(0xffffffffu, mx8, 2));

        float mn0 = fmaxf(m0, mx0), mn8 = fmaxf(m8, mx8);
        float c0 = __expf(m0 - mn0), c8 = __expf(m8 - mn8);
        float sum0 = 0.f, sum8 = 0.f;
        #pragma unroll
        for (int n = 0; n < 8; n++) {
            s[n][0] = __expf(s[n][0] - mn0); sum0 += s[n][0];
            s[n][1] = __expf(s[n][1] - mn0); sum0 += s[n][1];
            s[n][2] = __expf(s[n][2] - mn8); sum8 += s[n][2];
            s[n][3] = __expf(s[n][3] - mn8); sum8 += s[n][3];
        }
        sum0 += __shfl_xor_sync(0xffffffffu, sum0, 1);
        sum0 += __shfl_xor_sync(0xffffffffu, sum0, 2);
        sum8 += __shfl_xor_sync(0xffffffffu, sum8, 1);
        sum8 += __shfl_xor_sync(0xffffffffu, sum8, 2);
        l0 = l0 * c0 + sum0;
        l8 = l8 * c8 + sum8;
        m0 = mn0; m8 = mn8;

        #pragma unroll
        for (int n = 0; n < 8; n++) {
            o[n][0] *= c0; o[n][1] *= c0;
            o[n][2] *= c8; o[n][3] *= c8;
        }

        // ---- repack S -> P A-fragments in registers (no smem roundtrip) ----
        // A-frag for kg: keys 16kg+{2tig,2tig+1} (+8): rows g, g+8 ->
        //   [0]=s[2kg][0,1], [1]=s[2kg][2,3], [2]=s[2kg+1][0,1], [3]=s[2kg+1][2,3]
        unsigned ph[4][4], pl[4][4];
        #pragma unroll
        for (int kg = 0; kg < 4; kg++) {
            ph[kg][0] = sp_split(s[2 * kg][0],     s[2 * kg][1],     pl[kg][0]);
            ph[kg][1] = sp_split(s[2 * kg][2],     s[2 * kg][3],     pl[kg][1]);
            ph[kg][2] = sp_split(s[2 * kg + 1][0], s[2 * kg + 1][1], pl[kg][2]);
            ph[kg][3] = sp_split(s[2 * kg + 1][2], s[2 * kg + 1][3], pl[kg][3]);
        }

        // ---- O += P V : B via ldmatrix.x4 from V^T planes ----
        #pragma unroll
        for (int n = 0; n < 8; n++) {
            unsigned bh[8], bl[8];
            ldmat4(bh,     sV + AB_VH + n * 1024 + laneoff);
            ldmat4(bh + 4, sV + AB_VH + n * 1024 + 64 + laneoff);
            ldmat4(bl,     sV + AB_VL + n * 1024 + laneoff);
            ldmat4(bl + 4, sV + AB_VL + n * 1024 + 64 + laneoff);
            #pragma unroll
            for (int kg = 0; kg < 4; kg++) {
                MMAH(o[n], ph[kg], bh[kg * 2], bh[kg * 2 + 1]);
                MMAH(o[n], pl[kg], bh[kg * 2], bh[kg * 2 + 1]);
                MMAH(o[n], ph[kg], bl[kg * 2], bl[kg * 2 + 1]);
            }
        }
    }

    // ---- epilogue: normalize, store, fused absmax ----
    float inv0 = __fdiv_rn(1.0f, l0);
    float inv8 = __fdiv_rn(1.0f, l8);
    int qg = q0 + wid * 16 + g;
    float amax = 0.f;
    #pragma unroll
    for (int n = 0; n < 8; n++) {
        float x0 = o[n][0] * inv0, y0 = o[n][1] * inv0;
        float x8 = o[n][2] * inv8, y8 = o[n][3] * inv8;
        amax = fmaxf(amax, fmaxf(fmaxf(fabsf(x0), fabsf(y0)), fmaxf(fabsf(x8), fabsf(y8))));
        *(float2*)&g_attn[base + (size_t)qg * DIM + n * 8 + 2 * tig] = make_float2(x0, y0);
        *(float2*)&g_attn[base + (size_t)(qg + 8) * DIM + n * 8 + 2 * tig] = make_float2(x8, y8);
    }
    #pragma unroll
    for (int off = 16; off; off >>= 1) amax = fmaxf(amax, __shfl_xor_sync(0xffffffffu, amax, off));
    float* sred = (float*)(smc + AB_SRED);
    if (lane == 0) sred[wid] = amax;
    __syncthreads();
    if (tid == 0) {
        float mm = sred[0];
        #pragma unroll
        for (int i = 1; i < 8; i++) mm = fmaxf(mm, sred[i]);
        atomicMax(&g_absmax[5], __float_as_uint(mm));
    }
}

// ---------------- launch ----------------
extern "C" void kernel_launch(void* const* d_in, const int* in_sizes, int n_in,
                              void* d_out, int out_size) {
    const float* hidden = (const float*)d_in[0];
    const float* mask   = (const float*)d_in[1];
    const float* Wq = (const float*)d_in[2];
    const float* bq = (const float*)d_in[3];
    const float* Wk = (const float*)d_in[4];
    const float* bk = (const float*)d_in[5];
    const float* Wv = (const float*)d_in[6];
    const float* bv = (const float*)d_in[7];
    const float* Wo = (const float*)d_in[8];
    const float* bo = (const float*)d_in[9];
    float* out = (float*)d_out;

    cudaFuncSetAttribute(attn_k, cudaFuncAttributeMaxDynamicSharedMemorySize, AB_SMEM);
    const int GEMM_SMEM = 3 * STG_BYTES;

    absmax_all_k<<<dim3(256, 5), 256>>>(hidden, Wq, Wk, Wv, Wo);            // 1
    quant_all_k<<<dim3(256, 5), 256>>>(hidden, Wq, Wk, Wv, Wo);             // 2
    gemm_qkv_k<<<dim3(DIM / BN2, (BB * SS) / BM2, 3), 256, GEMM_SMEM>>>(bq, bk, bv); // 3
    attn_k<<<dim3(SS / 128, HH, BB), 256, AB_SMEM>>>(mask);                 // 4 <- ncu capture slot
    quant_attn_k<<<1024, 256>>>();                                          // 5
    gemm_o_k<<<dim3(DIM / BN2, (BB * SS) / BM2), 256, GEMM_SMEM>>>(bo, out); // 6
}

// round 11
// speedup vs baseline: 2.5618x; 2.5618x over previous
#include <cuda_runtime.h>
#include <cuda_bf16.h>
#include <cuda_fp16.h>

#define BB 2
#define SS 2048
#define DIM 1024
#define HH 16
#define HD 64
#define BSD (BB*SS*DIM)
#define DD  (DIM*DIM)

// ---------------- scratch ----------------
__device__ unsigned g_absmax[8];
__device__ float g_scales[8];
__device__ __align__(256) __nv_bfloat16 g_Xq[BSD];
__device__ __align__(256) __nv_bfloat16 g_Aq[BSD];
__device__ __align__(256) __nv_bfloat16 g_Wb[4][DD];
__device__ __align__(256) float g_Q[BSD];
__device__ __align__(256) __half g_Khi[BSD];   // [token][d] fp16 hi
__device__ __align__(256) __half g_Klo[BSD];   // [token][d] fp16 lo
__device__ __align__(256) __half g_VThi[BSD];  // [b,h][d][token] fp16 hi (transposed)
__device__ __align__(256) __half g_VTlo[BSD];
__device__ __align__(256) float g_attn[BSD];

// ---------------- helpers ----------------
__device__ __forceinline__ void cpasync16(unsigned saddr, const void* g) {
    asm volatile("cp.async.cg.shared.global [%0], [%1], 16;" :: "r"(saddr), "l"(g));
}
#define CP_COMMIT asm volatile("cp.async.commit_group;")
#define CP_WAIT(n) asm volatile("cp.async.wait_group %0;" :: "n"(n))

__device__ __forceinline__ void ldmat4(unsigned* r, unsigned addr) {
    asm volatile("ldmatrix.sync.aligned.m8n8.x4.shared.b16 {%0,%1,%2,%3},[%4];"
        : "=r"(r[0]), "=r"(r[1]), "=r"(r[2]), "=r"(r[3]) : "r"(addr));
}
__device__ __forceinline__ void mma16816(float* c, const unsigned* a, const unsigned* b) {
    asm volatile("mma.sync.aligned.m16n8k16.row.col.f32.bf16.bf16.f32 "
        "{%0,%1,%2,%3},{%4,%5,%6,%7},{%8,%9},{%0,%1,%2,%3};"
        : "+f"(c[0]), "+f"(c[1]), "+f"(c[2]), "+f"(c[3])
        : "r"(a[0]), "r"(a[1]), "r"(a[2]), "r"(a[3]), "r"(b[0]), "r"(b[1]));
}
// fp16 MMA, fp32 accumulate
#define MMAH(c, a, b0, b1) \
  asm volatile("mma.sync.aligned.m16n8k16.row.col.f32.f16.f16.f32 " \
    "{%0,%1,%2,%3},{%4,%5,%6,%7},{%8,%9},{%0,%1,%2,%3};" \
    : "+f"(c[0]), "+f"(c[1]), "+f"(c[2]), "+f"(c[3]) \
    : "r"(a[0]), "r"(a[1]), "r"(a[2]), "r"(a[3]), "r"(b0), "r"(b1))

// split (x,y) into packed fp16 hi/lo half2 pairs (Dekker)
__device__ __forceinline__ unsigned sp_split(float x, float y, unsigned& lo) {
    __half hx = __float2half_rn(x), hy = __float2half_rn(y);
    __half lx = __float2half_rn(x - __half2float(hx));
    __half ly = __float2half_rn(y - __half2float(hy));
    __half2 H = __halves2half2(hx, hy), L = __halves2half2(lx, ly);
    lo = *(unsigned*)&L;
    return *(unsigned*)&H;
}

// ---------------- batched absmax ----------------
__global__ void absmax_all_k(const float* __restrict__ h,
                             const float* w0, const float* w1,
                             const float* w2, const float* w3) {
    int y = blockIdx.y;
    const float* x = y == 0 ? h : y == 1 ? w0 : y == 2 ? w1 : y == 3 ? w2 : w3;
    int n4 = (y == 0 ? BSD : DD) >> 2;
    const float4* x4 = (const float4*)x;
    float m = 0.f;
    int stride = gridDim.x * blockDim.x;
    for (int i = blockIdx.x * blockDim.x + threadIdx.x; i < n4; i += stride) {
        float4 v = x4[i];
        m = fmaxf(m, fmaxf(fmaxf(fabsf(v.x), fabsf(v.y)), fmaxf(fabsf(v.z), fabsf(v.w))));
    }
    #pragma unroll
    for (int o = 16; o; o >>= 1) m = fmaxf(m, __shfl_xor_sync(0xffffffffu, m, o));
    __shared__ float sm[8];
    if ((threadIdx.x & 31) == 0) sm[threadIdx.x >> 5] = m;
    __syncthreads();
    if (threadIdx.x < 32) {
        m = (threadIdx.x < 8u) ? sm[threadIdx.x] : 0.f;
        #pragma unroll
        for (int o = 4; o; o >>= 1) m = fmaxf(m, __shfl_xor_sync(0xffffffffu, m, o));
        if (threadIdx.x == 0) atomicMax(&g_absmax[y], __float_as_uint(m));
    }
}

// ---------------- batched quantize ----------------
__global__ void quant_all_k(const float* __restrict__ h,
                            const float* w0, const float* w1,
                            const float* w2, const float* w3) {
    int y = blockIdx.y;
    const float* x = y == 0 ? h : y == 1 ? w0 : y == 2 ? w1 : y == 3 ? w2 : w3;
    __nv_bfloat16* out = y == 0 ? g_Xq : g_Wb[y - 1];
    int n4 = (y == 0 ? BSD : DD) >> 2;
    float s = fmaxf(__fdiv_rn(__uint_as_float(g_absmax[y]), 127.0f), 1e-8f);
    if (blockIdx.x == 0 && threadIdx.x == 0) g_scales[y] = s;
    int stride = gridDim.x * blockDim.x;
    for (int i = blockIdx.x * blockDim.x + threadIdx.x; i < n4; i += stride) {
        float4 v = ((const float4*)x)[i];
        __nv_bfloat162 lo = __floats2bfloat162_rn(rintf(__fdiv_rn(v.x, s)), rintf(__fdiv_rn(v.y, s)));
        __nv_bfloat162 hi = __floats2bfloat162_rn(rintf(__fdiv_rn(v.z, s)), rintf(__fdiv_rn(v.w, s)));
        uint2 pack;
        pack.x = *(unsigned*)&lo;
        pack.y = *(unsigned*)&hi;
        ((uint2*)out)[i] = pack;
    }
}

// ---------------- attn quantize ----------------
__global__ void quant_attn_k() {
    float s = fmaxf(__fdiv_rn(__uint_as_float(g_absmax[5]), 127.0f), 1e-8f);
    if (blockIdx.x == 0 && threadIdx.x == 0) g_scales[5] = s;
    int stride = gridDim.x * blockDim.x;
    for (int i = blockIdx.x * blockDim.x + threadIdx.x; i < (BSD >> 2); i += stride) {
        float4 v = ((const float4*)g_attn)[i];
        __nv_bfloat162 lo = __floats2bfloat162_rn(rintf(__fdiv_rn(v.x, s)), rintf(__fdiv_rn(v.y, s)));
        __nv_bfloat162 hi = __floats2bfloat162_rn(rintf(__fdiv_rn(v.z, s)), rintf(__fdiv_rn(v.w, s)));
        uint2 pack;
        pack.x = *(unsigned*)&lo;
        pack.y = *(unsigned*)&hi;
        ((uint2*)g_Aq)[i] = pack;
    }
}

// ================= pipelined bf16 GEMM core (unchanged) =================
#define BM2 128
#define BN2 64
#define BK2 32
#define PKB 80
#define STG_BYTES ((BM2 + BN2) * PKB)
#define KTILES (DIM / BK2)

__device__ __forceinline__ void gemm_body(const __nv_bfloat16* __restrict__ A,
                                          const __nv_bfloat16* __restrict__ B,
                                          const float* __restrict__ bias,
                                          float* __restrict__ cext, int c_sel,
                                          float scale, char* sm2) {
    const int rb = blockIdx.y * BM2, cb = blockIdx.x * BN2;
    const int tid = threadIdx.x, wid = tid >> 5, lane = tid & 31;
    const unsigned sbase = (unsigned)__cvta_generic_to_shared(sm2);

    const int wm = wid & 3, wn = wid >> 2;
    const int a_row = wm * 32 + (lane & 7) + ((lane >> 3) & 1) * 8;
    const int a_koff = (lane >> 4) * 8;
    const int b_row = wn * 32 + (lane & 7) + (lane >> 4) * 8;
    const int b_koff = ((lane >> 3) & 1) * 8;

    float c[2][4][4];
    #pragma unroll
    for (int mt = 0; mt < 2; mt++)
        #pragma unroll
        for (int nt = 0; nt < 4; nt++)
            #pragma unroll
            for (int e = 0; e < 4; e++) c[mt][nt][e] = 0.f;

    auto issue = [&](int ki) {
        int kt = ki * BK2;
        unsigned s = sbase + (ki % 3) * STG_BYTES;
        #pragma unroll
        for (int r2 = 0; r2 < 2; r2++) {
            int cidx = tid + r2 * 256;
            int row = cidx >> 2, ch = cidx & 3;
            cpasync16(s + row * PKB + ch * 16, A + (size_t)(rb + row) * DIM + kt + ch * 8);
        }
        {
            int row = tid >> 2, ch = tid & 3;
            cpasync16(s + BM2 * PKB + row * PKB + ch * 16, B + (size_t)(cb + row) * DIM + kt + ch * 8);
        }
        CP_COMMIT;
    };

    issue(0);
    issue(1);

    for (int i = 0; i < KTILES; i++) {
        if (i + 1 < KTILES) { CP_WAIT(1); } else { CP_WAIT(0); }
        __syncthreads();
        if (i + 2 < KTILES) issue(i + 2);
        unsigned s = sbase + (i % 3) * STG_BYTES;
        #pragma unroll
        for (int ks = 0; ks < BK2; ks += 16) {
            unsigned af[2][4], bf[2][4];
            ldmat4(af[0], s + a_row * PKB + (ks + a_koff) * 2);
            ldmat4(af[1], s + (a_row + 16) * PKB + (ks + a_koff) * 2);
            ldmat4(bf[0], s + BM2 * PKB + b_row * PKB + (ks + b_koff) * 2);
            ldmat4(bf[1], s + BM2 * PKB + (b_row + 16) * PKB + (ks + b_koff) * 2);
            #pragma unroll
            for (int mt = 0; mt < 2; mt++)
                #pragma unroll
                for (int nt = 0; nt < 4; nt++)
                    mma16816(c[mt][nt], af[mt], &bf[nt >> 1][(nt & 1) * 2]);
        }
        __syncthreads();
    }

    const int g = lane >> 2, tig = lane & 3;
    #pragma unroll
    for (int mt = 0; mt < 2; mt++) {
        #pragma unroll
        for (int nt = 0; nt < 4; nt++) {
            int col = cb + wn * 32 + nt * 8 + 2 * tig;
            float2 bv = *(const float2*)&bias[col];
            #pragma unroll
            for (int half = 0; half < 2; half++) {
                int row = rb + wm * 32 + mt * 16 + g + half * 8;
                float x = c[mt][nt][half * 2]     * scale + bv.x;
                float y = c[mt][nt][half * 2 + 1] * scale + bv.y;
                size_t off = (size_t)row * DIM + col;
                if (c_sel == 0) {
                    *(float2*)&g_Q[off] = make_float2(x, y);
                } else if (c_sel == 1) {
                    unsigned lo, hi = sp_split(x, y, lo);
                    *(unsigned*)&g_Khi[off] = hi;
                    *(unsigned*)&g_Klo[off] = lo;
                } else if (c_sel == 2) {
                    __half hx = __float2half_rn(x), hy = __float2half_rn(y);
                    __half lx = __float2half_rn(x - __half2float(hx));
                    __half ly = __float2half_rn(y - __half2float(hy));
                    int brow = row >> 11, tok = row & (SS - 1);
                    int hh = col >> 6, dd = col & 63;
                    size_t offT = ((size_t)((brow * HH + hh) * HD + dd)) * SS + tok;
                    g_VThi[offT] = hx;      g_VTlo[offT] = lx;
                    g_VThi[offT + SS] = hy; g_VTlo[offT + SS] = ly;
                } else {
                    *(float2*)&cext[off] = make_float2(x, y);
                }
            }
        }
    }
}

__global__ void __launch_bounds__(256) gemm_qkv_k(const float* __restrict__ bq,
                                                  const float* __restrict__ bk,
                                                  const float* __restrict__ bv) {
    extern __shared__ char sm2[];
    int z = blockIdx.z;
    const float* bias = z == 0 ? bq : z == 1 ? bk : bv;
    float scale = g_scales[0] * g_scales[1 + z];
    gemm_body(g_Xq, g_Wb[z], bias, nullptr, z, scale, sm2);
}

__global__ void __launch_bounds__(256) gemm_o_k(const float* __restrict__ bo,
                                                float* __restrict__ out) {
    extern __shared__ char sm2[];
    float scale = g_scales[5] * g_scales[4];
    gemm_body(g_Aq, g_Wb[3], bo, out, 3, scale, sm2);
}

// ================= fp16 3-term flash attention, reg-resident P, LDSM, padded rows ====
// BQ=128 (8 warps x 16 q-rows), BK=64, double-buffered K/V, 256 threads, 2 CTAs/SM.
// K smem:  [64 keys][128B dims, stride 144B]   (hi and lo planes)
// V smem:  [64 dims][128B keys, stride 144B]   (hi and lo planes, from transposed V)
// 144B row stride: LDSM's 8 rows/matrix start at banks {0,4,...,28} -> conflict-free.

#define KROW 144
#define PLANE (64 * KROW)       /* 9216 bytes */

#define AB_KH 0                 /* 2 bufs x 9216 */
#define AB_KL (2 * PLANE)       /* 18432 */
#define AB_VH (4 * PLANE)       /* 36864 */
#define AB_VL (6 * PLANE)       /* 55296 */
#define AB_MS (8 * PLANE)       /* 73728: 2 x 256B mask */
#define AB_SRED (AB_MS + 512)   /* 74240 */
#define AB_SMEM (AB_SRED + 32)  /* 74272 */

__global__ void __launch_bounds__(256, 2) attn_k(const float* __restrict__ mask) {
    extern __shared__ char smc[];
    const unsigned sb = (unsigned)__cvta_generic_to_shared(smc);

    const int b = blockIdx.z, h = blockIdx.y;
    const int q0 = blockIdx.x * 128;
    const int tid = threadIdx.x;
    const int wid = tid >> 5, lane = tid & 31;
    const int g = lane >> 2, tig = lane & 3;
    const size_t base = (size_t)b * SS * DIM + (size_t)h * HD;
    const size_t baseT = (size_t)(b * HH + h) * HD * SS;

    // ldmatrix lane offset within a plane: row (lane&7), matrix index (lane>>3) along 16B cols
    const unsigned laneoff = (lane & 7) * KROW + (lane >> 3) * 16;

    // ---- Q fragments straight from gmem (hi/lo fp16, 0.125 folded) ----
    unsigned qh[4][4], ql[4][4];
    {
        const float* Qr0 = &g_Q[base + (size_t)(q0 + wid * 16 + g) * DIM];
        const float* Qr8 = Qr0 + 8 * DIM;
        #pragma unroll
        for (int kg = 0; kg < 4; kg++) {
            float2 v0 = *(const float2*)&Qr0[kg * 16 + 2 * tig];
            float2 v1 = *(const float2*)&Qr8[kg * 16 + 2 * tig];
            float2 v2 = *(const float2*)&Qr0[kg * 16 + 2 * tig + 8];
            float2 v3 = *(const float2*)&Qr8[kg * 16 + 2 * tig + 8];
            qh[kg][0] = sp_split(v0.x * 0.125f, v0.y * 0.125f, ql[kg][0]);
            qh[kg][1] = sp_split(v1.x * 0.125f, v1.y * 0.125f, ql[kg][1]);
            qh[kg][2] = sp_split(v2.x * 0.125f, v2.y * 0.125f, ql[kg][2]);
            qh[kg][3] = sp_split(v3.x * 0.125f, v3.y * 0.125f, ql[kg][3]);
        }
    }

    // tile loader: 4 planes x 64 rows x 128B (stride 144B), one commit group
    auto issue_tile = [&](int kt, int buf) {
        const char* gKh = (const char*)&g_Khi[base + (size_t)kt * DIM];
        const char* gKl = (const char*)&g_Klo[base + (size_t)kt * DIM];
        const char* gVh = (const char*)g_VThi + 2 * (baseT + kt);
        const char* gVl = (const char*)g_VTlo + 2 * (baseT + kt);
        unsigned o = buf * PLANE;
        #pragma unroll
        for (int c = 0; c < 2; c++) {
            int idx = tid + c * 256;
            int r = idx >> 3, ch = idx & 7;
            unsigned so = o + r * KROW + ch * 16;
            cpasync16(sb + AB_KH + so, gKh + (size_t)r * (DIM * 2) + ch * 16);
            cpasync16(sb + AB_KL + so, gKl + (size_t)r * (DIM * 2) + ch * 16);
            cpasync16(sb + AB_VH + so, gVh + (size_t)r * (SS * 2) + ch * 16);
            cpasync16(sb + AB_VL + so, gVl + (size_t)r * (SS * 2) + ch * 16);
        }
        if (tid < 16)
            cpasync16(sb + AB_MS + buf * 256 + tid * 16,
                      (const char*)&mask[(size_t)b * SS + kt] + tid * 16);
        CP_COMMIT;
    };

    issue_tile(0, 0);

    float m0 = -1e30f, m8 = -1e30f, l0 = 0.f, l8 = 0.f;
    float o[8][4];
    #pragma unroll
    for (int n = 0; n < 8; n++)
        #pragma unroll
        for (int e = 0; e < 4; e++) o[n][e] = 0.f;

    for (int it = 0; it < SS / 64; it++) {
        const int cur = it & 1;
        CP_WAIT(0);
        __syncthreads();     // buffer cur ready; all warps done with buffer 1-cur
        if (it + 1 < SS / 64) issue_tile((it + 1) * 64, 1 - cur);

        const unsigned bufo = cur * PLANE;
        const float* Mc = (const float*)(smc + AB_MS + cur * 256);

        // ---- S = (Q/8) K^T : B via ldmatrix.x4 ----
        float s[8][4];
        #pragma unroll
        for (int n = 0; n < 8; n++)
            #pragma unroll
            for (int e = 0; e < 4; e++) s[n][e] = 0.f;

        #pragma unroll
        for (int n = 0; n < 8; n++) {
            unsigned bh[8], bl[8];
            unsigned rowb = bufo + n * (8 * KROW) + laneoff;
            ldmat4(bh,     sb + AB_KH + rowb);        // kg0,1
            ldmat4(bh + 4, sb + AB_KH + rowb + 64);   // kg2,3
            ldmat4(bl,     sb + AB_KL + rowb);
            ldmat4(bl + 4, sb + AB_KL + rowb + 64);
            #pragma unroll
            for (int kg = 0; kg < 4; kg++) {
                MMAH(s[n], qh[kg], bh[kg * 2], bh[kg * 2 + 1]);
                MMAH(s[n], ql[kg], bh[kg * 2], bh[kg * 2 + 1]);
                MMAH(s[n], qh[kg], bl[kg * 2], bl[kg * 2 + 1]);
            }
        }

        // ---- online softmax (rows g / g+8) ----
        float mx0 = -1e30f, mx8 = -1e30f;
        #pragma unroll
        for (int n = 0; n < 8; n++) {
            float2 mm = *(const float2*)&Mc[n * 8 + 2 * tig];
            float bx = mm.x * 10000.0f - 10000.0f;
            float by = mm.y * 10000.0f - 10000.0f;
            s[n][0] += bx; s[n][1] += by;
            s[n][2] += bx; s[n][3] += by;
            mx0 = fmaxf(mx0, fmaxf(s[n][0], s[n][1]));
            mx8 = fmaxf(mx8, fmaxf(s[n][2], s[n][3]));
        }
        mx0 = fmaxf(mx0, __shfl_xor_sync(0xffffffffu, mx0, 1));
        mx0 = fmaxf(mx0, __shfl_xor_sync(0xffffffffu, mx0, 2));
        mx8 = fmaxf(mx8, __shfl_xor_sync(0xffffffffu, mx8, 1));
        mx8 = fmaxf(mx8, __shfl_xor_sync(0xffffffffu, mx8, 2));

        float mn0 = fmaxf(m0, mx0), mn8 = fmaxf(m8, mx8);
        float c0 = __expf(m0 - mn0), c8 = __expf(m8 - mn8);
        float sum0 = 0.f, sum8 = 0.f;
        #pragma unroll
        for (int n = 0; n < 8; n++) {
            s[n][0] = __expf(s[n][0] - mn0); sum0 += s[n][0];
            s[n][1] = __expf(s[n][1] - mn0); sum0 += s[n][1];
            s[n][2] = __expf(s[n][2] - mn8); sum8 += s[n][2];
            s[n][3] = __expf(s[n][3] - mn8); sum8 += s[n][3];
        }
        sum0 += __shfl_xor_sync(0xffffffffu, sum0, 1);
        sum0 += __shfl_xor_sync(0xffffffffu, sum0, 2);
        sum8 += __shfl_xor_sync(0xffffffffu, sum8, 1);
        sum8 += __shfl_xor_sync(0xffffffffu, sum8, 2);
        l0 = l0 * c0 + sum0;
        l8 = l8 * c8 + sum8;
        m0 = mn0; m8 = mn8;

        #pragma unroll
        for (int n = 0; n < 8; n++) {
            o[n][0] *= c0; o[n][1] *= c0;
            o[n][2] *= c8; o[n][3] *= c8;
        }

        // ---- repack S -> P A-fragments in registers (no smem roundtrip) ----
        unsigned ph[4][4], pl[4][4];
        #pragma unroll
        for (int kg = 0; kg < 4; kg++) {
            ph[kg][0] = sp_split(s[2 * kg][0],     s[2 * kg][1],     pl[kg][0]);
            ph[kg][1] = sp_split(s[2 * kg][2],     s[2 * kg][3],     pl[kg][1]);
            ph[kg][2] = sp_split(s[2 * kg + 1][0], s[2 * kg + 1][1], pl[kg][2]);
            ph[kg][3] = sp_split(s[2 * kg + 1][2], s[2 * kg + 1][3], pl[kg][3]);
        }

        // ---- O += P V : B via ldmatrix.x4 from V^T planes ----
        #pragma unroll
        for (int n = 0; n < 8; n++) {
            unsigned bh[8], bl[8];
            unsigned rowb = bufo + n * (8 * KROW) + laneoff;
            ldmat4(bh,     sb + AB_VH + rowb);
            ldmat4(bh + 4, sb + AB_VH + rowb + 64);
            ldmat4(bl,     sb + AB_VL + rowb);
            ldmat4(bl + 4, sb + AB_VL + rowb + 64);
            #pragma unroll
            for (int kg = 0; kg < 4; kg++) {
                MMAH(o[n], ph[kg], bh[kg * 2], bh[kg * 2 + 1]);
                MMAH(o[n], pl[kg], bh[kg * 2], bh[kg * 2 + 1]);
                MMAH(o[n], ph[kg], bl[kg * 2], bl[kg * 2 + 1]);
            }
        }
    }

    // ---- epilogue: normalize, store, fused absmax ----
    float inv0 = __fdiv_rn(1.0f, l0);
    float inv8 = __fdiv_rn(1.0f, l8);
    int qg = q0 + wid * 16 + g;
    float amax = 0.f;
    #pragma unroll
    for (int n = 0; n < 8; n++) {
        float x0 = o[n][0] * inv0, y0 = o[n][1] * inv0;
        float x8 = o[n][2] * inv8, y8 = o[n][3] * inv8;
        amax = fmaxf(amax, fmaxf(fmaxf(fabsf(x0), fabsf(y0)), fmaxf(fabsf(x8), fabsf(y8))));
        *(float2*)&g_attn[base + (size_t)qg * DIM + n * 8 + 2 * tig] = make_float2(x0, y0);
        *(float2*)&g_attn[base + (size_t)(qg + 8) * DIM + n * 8 + 2 * tig] = make_float2(x8, y8);
    }
    #pragma unroll
    for (int off = 16; off; off >>= 1) amax = fmaxf(amax, __shfl_xor_sync(0xffffffffu, amax, off));
    float* sred = (float*)(smc + AB_SRED);
    if (lane == 0) sred[wid] = amax;
    __syncthreads();
    if (tid == 0) {
        float mm = sred[0];
        #pragma unroll
        for (int i = 1; i < 8; i++) mm = fmaxf(mm, sred[i]);
        atomicMax(&g_absmax[5], __float_as_uint(mm));
    }
}

// ---------------- launch ----------------
extern "C" void kernel_launch(void* const* d_in, const int* in_sizes, int n_in,
                              void* d_out, int out_size) {
    const float* hidden = (const float*)d_in[0];
    const float* mask   = (const float*)d_in[1];
    const float* Wq = (const float*)d_in[2];
    const float* bq = (const float*)d_in[3];
    const float* Wk = (const float*)d_in[4];
    const float* bk = (const float*)d_in[5];
    const float* Wv = (const float*)d_in[6];
    const float* bv = (const float*)d_in[7];
    const float* Wo = (const float*)d_in[8];
    const float* bo = (const float*)d_in[9];
    float* out = (float*)d_out;

    cudaFuncSetAttribute(attn_k, cudaFuncAttributeMaxDynamicSharedMemorySize, AB_SMEM);
    const int GEMM_SMEM = 3 * STG_BYTES;

    absmax_all_k<<<dim3(256, 5), 256>>>(hidden, Wq, Wk, Wv, Wo);            // 1
    quant_all_k<<<dim3(256, 5), 256>>>(hidden, Wq, Wk, Wv, Wo);             // 2
    gemm_qkv_k<<<dim3(DIM / BN2, (BB * SS) / BM2, 3), 256, GEMM_SMEM>>>(bq, bk, bv); // 3
    attn_k<<<dim3(SS / 128, HH, BB), 256, AB_SMEM>>>(mask);                 // 4 <- ncu capture slot
    quant_attn_k<<<1024, 256>>>();                                          // 5
    gemm_o_k<<<dim3(DIM / BN2, (BB * SS) / BM2), 256, GEMM_SMEM>>>(bo, out); // 6
}

// round 12
// speedup vs baseline: 2.7243x; 1.0634x over previous
#include <cuda_runtime.h>
#include <cuda_bf16.h>
#include <cuda_fp16.h>

#define BB 2
#define SS 2048
#define DIM 1024
#define HH 16
#define HD 64
#define BSD (BB*SS*DIM)
#define DD  (DIM*DIM)

// ---------------- scratch ----------------
__device__ unsigned g_absmax[8];
__device__ float g_scales[8];
__device__ __align__(256) __nv_bfloat16 g_Xq[BSD];
__device__ __align__(256) __nv_bfloat16 g_Aq[BSD];
__device__ __align__(256) __nv_bfloat16 g_Wb[4][DD];
__device__ __align__(256) float g_Q[BSD];
__device__ __align__(256) __half g_Khi[BSD];   // [token][d] fp16 hi
__device__ __align__(256) __half g_Klo[BSD];   // [token][d] fp16 lo
__device__ __align__(256) __half g_VThi[BSD];  // [b,h][d][token] fp16 hi (transposed)
__device__ __align__(256) __half g_VTlo[BSD];
__device__ __align__(256) float g_attn[BSD];

// ---------------- helpers ----------------
__device__ __forceinline__ void cpasync16(unsigned saddr, const void* g) {
    asm volatile("cp.async.cg.shared.global [%0], [%1], 16;" :: "r"(saddr), "l"(g));
}
#define CP_COMMIT asm volatile("cp.async.commit_group;")
#define CP_WAIT(n) asm volatile("cp.async.wait_group %0;" :: "n"(n))

__device__ __forceinline__ void ldmat4(unsigned* r, unsigned addr) {
    asm volatile("ldmatrix.sync.aligned.m8n8.x4.shared.b16 {%0,%1,%2,%3},[%4];"
        : "=r"(r[0]), "=r"(r[1]), "=r"(r[2]), "=r"(r[3]) : "r"(addr));
}
__device__ __forceinline__ void mma16816(float* c, const unsigned* a, const unsigned* b) {
    asm volatile("mma.sync.aligned.m16n8k16.row.col.f32.bf16.bf16.f32 "
        "{%0,%1,%2,%3},{%4,%5,%6,%7},{%8,%9},{%0,%1,%2,%3};"
        : "+f"(c[0]), "+f"(c[1]), "+f"(c[2]), "+f"(c[3])
        : "r"(a[0]), "r"(a[1]), "r"(a[2]), "r"(a[3]), "r"(b[0]), "r"(b[1]));
}
// fp16 MMA, fp32 accumulate
#define MMAH(c, a, b0, b1) \
  asm volatile("mma.sync.aligned.m16n8k16.row.col.f32.f16.f16.f32 " \
    "{%0,%1,%2,%3},{%4,%5,%6,%7},{%8,%9},{%0,%1,%2,%3};" \
    : "+f"(c[0]), "+f"(c[1]), "+f"(c[2]), "+f"(c[3]) \
    : "r"(a[0]), "r"(a[1]), "r"(a[2]), "r"(a[3]), "r"(b0), "r"(b1))

// split (x,y) into packed fp16 hi/lo half2 pairs (Dekker)
__device__ __forceinline__ unsigned sp_split(float x, float y, unsigned& lo) {
    __half hx = __float2half_rn(x), hy = __float2half_rn(y);
    __half lx = __float2half_rn(x - __half2float(hx));
    __half ly = __float2half_rn(y - __half2float(hy));
    __half2 H = __halves2half2(hx, hy), L = __halves2half2(lx, ly);
    lo = *(unsigned*)&L;
    return *(unsigned*)&H;
}

// ---------------- batched absmax ----------------
__global__ void absmax_all_k(const float* __restrict__ h,
                             const float* w0, const float* w1,
                             const float* w2, const float* w3) {
    int y = blockIdx.y;
    const float* x = y == 0 ? h : y == 1 ? w0 : y == 2 ? w1 : y == 3 ? w2 : w3;
    int n4 = (y == 0 ? BSD : DD) >> 2;
    const float4* x4 = (const float4*)x;
    float m = 0.f;
    int stride = gridDim.x * blockDim.x;
    for (int i = blockIdx.x * blockDim.x + threadIdx.x; i < n4; i += stride) {
        float4 v = x4[i];
        m = fmaxf(m, fmaxf(fmaxf(fabsf(v.x), fabsf(v.y)), fmaxf(fabsf(v.z), fabsf(v.w))));
    }
    #pragma unroll
    for (int o = 16; o; o >>= 1) m = fmaxf(m, __shfl_xor_sync(0xffffffffu, m, o));
    __shared__ float sm[8];
    if ((threadIdx.x & 31) == 0) sm[threadIdx.x >> 5] = m;
    __syncthreads();
    if (threadIdx.x < 32) {
        m = (threadIdx.x < 8u) ? sm[threadIdx.x] : 0.f;
        #pragma unroll
        for (int o = 4; o; o >>= 1) m = fmaxf(m, __shfl_xor_sync(0xffffffffu, m, o));
        if (threadIdx.x == 0) atomicMax(&g_absmax[y], __float_as_uint(m));
    }
}

// ---------------- batched quantize ----------------
__global__ void quant_all_k(const float* __restrict__ h,
                            const float* w0, const float* w1,
                            const float* w2, const float* w3) {
    int y = blockIdx.y;
    const float* x = y == 0 ? h : y == 1 ? w0 : y == 2 ? w1 : y == 3 ? w2 : w3;
    __nv_bfloat16* out = y == 0 ? g_Xq : g_Wb[y - 1];
    int n4 = (y == 0 ? BSD : DD) >> 2;
    float s = fmaxf(__fdiv_rn(__uint_as_float(g_absmax[y]), 127.0f), 1e-8f);
    if (blockIdx.x == 0 && threadIdx.x == 0) g_scales[y] = s;
    int stride = gridDim.x * blockDim.x;
    for (int i = blockIdx.x * blockDim.x + threadIdx.x; i < n4; i += stride) {
        float4 v = ((const float4*)x)[i];
        __nv_bfloat162 lo = __floats2bfloat162_rn(rintf(__fdiv_rn(v.x, s)), rintf(__fdiv_rn(v.y, s)));
        __nv_bfloat162 hi = __floats2bfloat162_rn(rintf(__fdiv_rn(v.z, s)), rintf(__fdiv_rn(v.w, s)));
        uint2 pack;
        pack.x = *(unsigned*)&lo;
        pack.y = *(unsigned*)&hi;
        ((uint2*)out)[i] = pack;
    }
}

// ---------------- attn quantize ----------------
__global__ void quant_attn_k() {
    float s = fmaxf(__fdiv_rn(__uint_as_float(g_absmax[5]), 127.0f), 1e-8f);
    if (blockIdx.x == 0 && threadIdx.x == 0) g_scales[5] = s;
    int stride = gridDim.x * blockDim.x;
    for (int i = blockIdx.x * blockDim.x + threadIdx.x; i < (BSD >> 2); i += stride) {
        float4 v = ((const float4*)g_attn)[i];
        __nv_bfloat162 lo = __floats2bfloat162_rn(rintf(__fdiv_rn(v.x, s)), rintf(__fdiv_rn(v.y, s)));
        __nv_bfloat162 hi = __floats2bfloat162_rn(rintf(__fdiv_rn(v.z, s)), rintf(__fdiv_rn(v.w, s)));
        uint2 pack;
        pack.x = *(unsigned*)&lo;
        pack.y = *(unsigned*)&hi;
        ((uint2*)g_Aq)[i] = pack;
    }
}

// ================= pipelined bf16 GEMM core (unchanged) =================
#define BM2 128
#define BN2 64
#define BK2 32
#define PKB 80
#define STG_BYTES ((BM2 + BN2) * PKB)
#define KTILES (DIM / BK2)

__device__ __forceinline__ void gemm_body(const __nv_bfloat16* __restrict__ A,
                                          const __nv_bfloat16* __restrict__ B,
                                          const float* __restrict__ bias,
                                          float* __restrict__ cext, int c_sel,
                                          float scale, char* sm2) {
    const int rb = blockIdx.y * BM2, cb = blockIdx.x * BN2;
    const int tid = threadIdx.x, wid = tid >> 5, lane = tid & 31;
    const unsigned sbase = (unsigned)__cvta_generic_to_shared(sm2);

    const int wm = wid & 3, wn = wid >> 2;
    const int a_row = wm * 32 + (lane & 7) + ((lane >> 3) & 1) * 8;
    const int a_koff = (lane >> 4) * 8;
    const int b_row = wn * 32 + (lane & 7) + (lane >> 4) * 8;
    const int b_koff = ((lane >> 3) & 1) * 8;

    float c[2][4][4];
    #pragma unroll
    for (int mt = 0; mt < 2; mt++)
        #pragma unroll
        for (int nt = 0; nt < 4; nt++)
            #pragma unroll
            for (int e = 0; e < 4; e++) c[mt][nt][e] = 0.f;

    auto issue = [&](int ki) {
        int kt = ki * BK2;
        unsigned s = sbase + (ki % 3) * STG_BYTES;
        #pragma unroll
        for (int r2 = 0; r2 < 2; r2++) {
            int cidx = tid + r2 * 256;
            int row = cidx >> 2, ch = cidx & 3;
            cpasync16(s + row * PKB + ch * 16, A + (size_t)(rb + row) * DIM + kt + ch * 8);
        }
        {
            int row = tid >> 2, ch = tid & 3;
            cpasync16(s + BM2 * PKB + row * PKB + ch * 16, B + (size_t)(cb + row) * DIM + kt + ch * 8);
        }
        CP_COMMIT;
    };

    issue(0);
    issue(1);

    for (int i = 0; i < KTILES; i++) {
        if (i + 1 < KTILES) { CP_WAIT(1); } else { CP_WAIT(0); }
        __syncthreads();
        if (i + 2 < KTILES) issue(i + 2);
        unsigned s = sbase + (i % 3) * STG_BYTES;
        #pragma unroll
        for (int ks = 0; ks < BK2; ks += 16) {
            unsigned af[2][4], bf[2][4];
            ldmat4(af[0], s + a_row * PKB + (ks + a_koff) * 2);
            ldmat4(af[1], s + (a_row + 16) * PKB + (ks + a_koff) * 2);
            ldmat4(bf[0], s + BM2 * PKB + b_row * PKB + (ks + b_koff) * 2);
            ldmat4(bf[1], s + BM2 * PKB + (b_row + 16) * PKB + (ks + b_koff) * 2);
            #pragma unroll
            for (int mt = 0; mt < 2; mt++)
                #pragma unroll
                for (int nt = 0; nt < 4; nt++)
                    mma16816(c[mt][nt], af[mt], &bf[nt >> 1][(nt & 1) * 2]);
        }
        __syncthreads();
    }

    const int g = lane >> 2, tig = lane & 3;
    #pragma unroll
    for (int mt = 0; mt < 2; mt++) {
        #pragma unroll
        for (int nt = 0; nt < 4; nt++) {
            int col = cb + wn * 32 + nt * 8 + 2 * tig;
            float2 bv = *(const float2*)&bias[col];
            #pragma unroll
            for (int half = 0; half < 2; half++) {
                int row = rb + wm * 32 + mt * 16 + g + half * 8;
                float x = c[mt][nt][half * 2]     * scale + bv.x;
                float y = c[mt][nt][half * 2 + 1] * scale + bv.y;
                size_t off = (size_t)row * DIM + col;
                if (c_sel == 0) {
                    *(float2*)&g_Q[off] = make_float2(x, y);
                } else if (c_sel == 1) {
                    unsigned lo, hi = sp_split(x, y, lo);
                    *(unsigned*)&g_Khi[off] = hi;
                    *(unsigned*)&g_Klo[off] = lo;
                } else if (c_sel == 2) {
                    __half hx = __float2half_rn(x), hy = __float2half_rn(y);
                    __half lx = __float2half_rn(x - __half2float(hx));
                    __half ly = __float2half_rn(y - __half2float(hy));
                    int brow = row >> 11, tok = row & (SS - 1);
                    int hh = col >> 6, dd = col & 63;
                    size_t offT = ((size_t)((brow * HH + hh) * HD + dd)) * SS + tok;
                    g_VThi[offT] = hx;      g_VTlo[offT] = lx;
                    g_VThi[offT + SS] = hy; g_VTlo[offT + SS] = ly;
                } else {
                    *(float2*)&cext[off] = make_float2(x, y);
                }
            }
        }
    }
}

__global__ void __launch_bounds__(256) gemm_qkv_k(const float* __restrict__ bq,
                                                  const float* __restrict__ bk,
                                                  const float* __restrict__ bv) {
    extern __shared__ char sm2[];
    int z = blockIdx.z;
    const float* bias = z == 0 ? bq : z == 1 ? bk : bv;
    float scale = g_scales[0] * g_scales[1 + z];
    gemm_body(g_Xq, g_Wb[z], bias, nullptr, z, scale, sm2);
}

__global__ void __launch_bounds__(256) gemm_o_k(const float* __restrict__ bo,
                                                float* __restrict__ out) {
    extern __shared__ char sm2[];
    float scale = g_scales[5] * g_scales[4];
    gemm_body(g_Aq, g_Wb[3], bo, out, 3, scale, sm2);
}

// ================= fp16 3-term flash attention, 32 q-rows/warp =================
// BQ=128 (4 warps x 32 q-rows), BK=64, double-buffered K/V (split K/V commit groups),
// 128 threads, 2 CTAs/SM. Fragment loads amortized over 2x rows -> LDS/work halved.
// K smem:  [64 keys][128B dims, stride 144B]  (hi, lo planes)
// V smem:  [64 dims][128B keys, stride 144B]  (hi, lo planes, transposed V)

#define KROW 144
#define PLANE (64 * KROW)       /* 9216 bytes */

#define AB_KH 0                 /* 2 bufs x 9216 */
#define AB_KL (2 * PLANE)
#define AB_VH (4 * PLANE)
#define AB_VL (6 * PLANE)
#define AB_MS (8 * PLANE)       /* 2 x 256B mask */
#define AB_SRED (AB_MS + 512)
#define AB_SMEM (AB_SRED + 32)

__global__ void __launch_bounds__(128, 2) attn_k(const float* __restrict__ mask) {
    extern __shared__ char smc[];
    const unsigned sb = (unsigned)__cvta_generic_to_shared(smc);

    const int b = blockIdx.z, h = blockIdx.y;
    const int q0 = blockIdx.x * 128;
    const int tid = threadIdx.x;
    const int wid = tid >> 5, lane = tid & 31;
    const int g = lane >> 2, tig = lane & 3;
    const size_t base = (size_t)b * SS * DIM + (size_t)h * HD;
    const size_t baseT = (size_t)(b * HH + h) * HD * SS;

    const unsigned laneoff = (lane & 7) * KROW + (lane >> 3) * 16;

    // ---- Q fragments for TWO 16-row halves (hi/lo fp16, 0.125 folded) ----
    unsigned qh0[4][4], ql0[4][4], qh1[4][4], ql1[4][4];
    {
        const float* Qa = &g_Q[base + (size_t)(q0 + wid * 32 + g) * DIM];        // rows +0,+8
        const float* Qb = Qa + 16 * DIM;                                         // rows +16,+24
        #pragma unroll
        for (int kg = 0; kg < 4; kg++) {
            float2 v0 = *(const float2*)&Qa[kg * 16 + 2 * tig];
            float2 v1 = *(const float2*)&Qa[8 * DIM + kg * 16 + 2 * tig];
            float2 v2 = *(const float2*)&Qa[kg * 16 + 2 * tig + 8];
            float2 v3 = *(const float2*)&Qa[8 * DIM + kg * 16 + 2 * tig + 8];
            qh0[kg][0] = sp_split(v0.x * 0.125f, v0.y * 0.125f, ql0[kg][0]);
            qh0[kg][1] = sp_split(v1.x * 0.125f, v1.y * 0.125f, ql0[kg][1]);
            qh0[kg][2] = sp_split(v2.x * 0.125f, v2.y * 0.125f, ql0[kg][2]);
            qh0[kg][3] = sp_split(v3.x * 0.125f, v3.y * 0.125f, ql0[kg][3]);
            v0 = *(const float2*)&Qb[kg * 16 + 2 * tig];
            v1 = *(const float2*)&Qb[8 * DIM + kg * 16 + 2 * tig];
            v2 = *(const float2*)&Qb[kg * 16 + 2 * tig + 8];
            v3 = *(const float2*)&Qb[8 * DIM + kg * 16 + 2 * tig + 8];
            qh1[kg][0] = sp_split(v0.x * 0.125f, v0.y * 0.125f, ql1[kg][0]);
            qh1[kg][1] = sp_split(v1.x * 0.125f, v1.y * 0.125f, ql1[kg][1]);
            qh1[kg][2] = sp_split(v2.x * 0.125f, v2.y * 0.125f, ql1[kg][2]);
            qh1[kg][3] = sp_split(v3.x * 0.125f, v3.y * 0.125f, ql1[kg][3]);
        }
    }

    // tile loader: K planes (+mask) in one commit group, V planes in another
    auto issue_K = [&](int kt, int buf) {
        const char* gKh = (const char*)&g_Khi[base + (size_t)kt * DIM];
        const char* gKl = (const char*)&g_Klo[base + (size_t)kt * DIM];
        unsigned o = buf * PLANE;
        #pragma unroll
        for (int c = 0; c < 4; c++) {
            int idx = tid + c * 128;
            int r = idx >> 3, ch = idx & 7;
            unsigned so = o + r * KROW + ch * 16;
            cpasync16(sb + AB_KH + so, gKh + (size_t)r * (DIM * 2) + ch * 16);
            cpasync16(sb + AB_KL + so, gKl + (size_t)r * (DIM * 2) + ch * 16);
        }
        if (tid < 16)
            cpasync16(sb + AB_MS + buf * 256 + tid * 16,
                      (const char*)&mask[(size_t)b * SS + kt] + tid * 16);
        CP_COMMIT;
    };
    auto issue_V = [&](int kt, int buf) {
        const char* gVh = (const char*)g_VThi + 2 * (baseT + kt);
        const char* gVl = (const char*)g_VTlo + 2 * (baseT + kt);
        unsigned o = buf * PLANE;
        #pragma unroll
        for (int c = 0; c < 4; c++) {
            int idx = tid + c * 128;
            int r = idx >> 3, ch = idx & 7;
            unsigned so = o + r * KROW + ch * 16;
            cpasync16(sb + AB_VH + so, gVh + (size_t)r * (SS * 2) + ch * 16);
            cpasync16(sb + AB_VL + so, gVl + (size_t)r * (SS * 2) + ch * 16);
        }
        CP_COMMIT;
    };

    issue_K(0, 0);
    issue_V(0, 0);

    float m00 = -1e30f, m08 = -1e30f, m10 = -1e30f, m18 = -1e30f;
    float l00 = 0.f, l08 = 0.f, l10 = 0.f, l18 = 0.f;
    float o0[8][4], o1[8][4];
    #pragma unroll
    for (int n = 0; n < 8; n++)
        #pragma unroll
        for (int e = 0; e < 4; e++) { o0[n][e] = 0.f; o1[n][e] = 0.f; }

    for (int it = 0; it < SS / 64; it++) {
        const int cur = it & 1;
        __syncthreads();     // all warps done with buffer 1-cur (prev iteration)
        if (it + 1 < SS / 64) {
            issue_K((it + 1) * 64, 1 - cur);
            issue_V((it + 1) * 64, 1 - cur);
            CP_WAIT(3);      // groups ordered: K(it) complete
        } else {
            CP_WAIT(1);
        }

        const unsigned bufo = cur * PLANE;
        const float* Mc = (const float*)(smc + AB_MS + cur * 256);

        // ---- S = (Q/8) K^T for both halves: shared B frags ----
        float s0[8][4], s1[8][4];
        #pragma unroll
        for (int n = 0; n < 8; n++)
            #pragma unroll
            for (int e = 0; e < 4; e++) { s0[n][e] = 0.f; s1[n][e] = 0.f; }

        #pragma unroll
        for (int n = 0; n < 8; n++) {
            unsigned bh[8], bl[8];
            unsigned rowb = bufo + n * (8 * KROW) + laneoff;
            ldmat4(bh,     sb + AB_KH + rowb);
            ldmat4(bh + 4, sb + AB_KH + rowb + 64);
            ldmat4(bl,     sb + AB_KL + rowb);
            ldmat4(bl + 4, sb + AB_KL + rowb + 64);
            #pragma unroll
            for (int kg = 0; kg < 4; kg++) {
                MMAH(s0[n], qh0[kg], bh[kg * 2], bh[kg * 2 + 1]);
                MMAH(s0[n], ql0[kg], bh[kg * 2], bh[kg * 2 + 1]);
                MMAH(s0[n], qh0[kg], bl[kg * 2], bl[kg * 2 + 1]);
                MMAH(s1[n], qh1[kg], bh[kg * 2], bh[kg * 2 + 1]);
                MMAH(s1[n], ql1[kg], bh[kg * 2], bh[kg * 2 + 1]);
                MMAH(s1[n], qh1[kg], bl[kg * 2], bl[kg * 2 + 1]);
            }
        }

        // ---- online softmax (4 row-groups) ----
        float mx00 = -1e30f, mx08 = -1e30f, mx10 = -1e30f, mx18 = -1e30f;
        #pragma unroll
        for (int n = 0; n < 8; n++) {
            float2 mm = *(const float2*)&Mc[n * 8 + 2 * tig];
            float bx = mm.x * 10000.0f - 10000.0f;
            float by = mm.y * 10000.0f - 10000.0f;
            s0[n][0] += bx; s0[n][1] += by; s0[n][2] += bx; s0[n][3] += by;
            s1[n][0] += bx; s1[n][1] += by; s1[n][2] += bx; s1[n][3] += by;
            mx00 = fmaxf(mx00, fmaxf(s0[n][0], s0[n][1]));
            mx08 = fmaxf(mx08, fmaxf(s0[n][2], s0[n][3]));
            mx10 = fmaxf(mx10, fmaxf(s1[n][0], s1[n][1]));
            mx18 = fmaxf(mx18, fmaxf(s1[n][2], s1[n][3]));
        }
        #pragma unroll
        for (int o = 1; o < 4; o <<= 1) {
            mx00 = fmaxf(mx00, __shfl_xor_sync(0xffffffffu, mx00, o));
            mx08 = fmaxf(mx08, __shfl_xor_sync(0xffffffffu, mx08, o));
            mx10 = fmaxf(mx10, __shfl_xor_sync(0xffffffffu, mx10, o));
            mx18 = fmaxf(mx18, __shfl_xor_sync(0xffffffffu, mx18, o));
        }
        float mn00 = fmaxf(m00, mx00), mn08 = fmaxf(m08, mx08);
        float mn10 = fmaxf(m10, mx10), mn18 = fmaxf(m18, mx18);
        float c00 = __expf(m00 - mn00), c08 = __expf(m08 - mn08);
        float c10 = __expf(m10 - mn10), c18 = __expf(m18 - mn18);
        float su00 = 0.f, su08 = 0.f, su10 = 0.f, su18 = 0.f;
        #pragma unroll
        for (int n = 0; n < 8; n++) {
            s0[n][0] = __expf(s0[n][0] - mn00); su00 += s0[n][0];
            s0[n][1] = __expf(s0[n][1] - mn00); su00 += s0[n][1];
            s0[n][2] = __expf(s0[n][2] - mn08); su08 += s0[n][2];
            s0[n][3] = __expf(s0[n][3] - mn08); su08 += s0[n][3];
            s1[n][0] = __expf(s1[n][0] - mn10); su10 += s1[n][0];
            s1[n][1] = __expf(s1[n][1] - mn10); su10 += s1[n][1];
            s1[n][2] = __expf(s1[n][2] - mn18); su18 += s1[n][2];
            s1[n][3] = __expf(s1[n][3] - mn18); su18 += s1[n][3];
        }
        #pragma unroll
        for (int o = 1; o < 4; o <<= 1) {
            su00 += __shfl_xor_sync(0xffffffffu, su00, o);
            su08 += __shfl_xor_sync(0xffffffffu, su08, o);
            su10 += __shfl_xor_sync(0xffffffffu, su10, o);
            su18 += __shfl_xor_sync(0xffffffffu, su18, o);
        }
        l00 = l00 * c00 + su00; l08 = l08 * c08 + su08;
        l10 = l10 * c10 + su10; l18 = l18 * c18 + su18;
        m00 = mn00; m08 = mn08; m10 = mn10; m18 = mn18;

        #pragma unroll
        for (int n = 0; n < 8; n++) {
            o0[n][0] *= c00; o0[n][1] *= c00; o0[n][2] *= c08; o0[n][3] *= c08;
            o1[n][0] *= c10; o1[n][1] *= c10; o1[n][2] *= c18; o1[n][3] *= c18;
        }

        // ---- repack S -> P A-fragments in registers ----
        unsigned ph0[4][4], pl0[4][4], ph1[4][4], pl1[4][4];
        #pragma unroll
        for (int kg = 0; kg < 4; kg++) {
            ph0[kg][0] = sp_split(s0[2 * kg][0],     s0[2 * kg][1],     pl0[kg][0]);
            ph0[kg][1] = sp_split(s0[2 * kg][2],     s0[2 * kg][3],     pl0[kg][1]);
            ph0[kg][2] = sp_split(s0[2 * kg + 1][0], s0[2 * kg + 1][1], pl0[kg][2]);
            ph0[kg][3] = sp_split(s0[2 * kg + 1][2], s0[2 * kg + 1][3], pl0[kg][3]);
            ph1[kg][0] = sp_split(s1[2 * kg][0],     s1[2 * kg][1],     pl1[kg][0]);
            ph1[kg][1] = sp_split(s1[2 * kg][2],     s1[2 * kg][3],     pl1[kg][1]);
            ph1[kg][2] = sp_split(s1[2 * kg + 1][0], s1[2 * kg + 1][1], pl1[kg][2]);
            ph1[kg][3] = sp_split(s1[2 * kg + 1][2], s1[2 * kg + 1][3], pl1[kg][3]);
        }

        if (it + 1 < SS / 64) { CP_WAIT(2); } else { CP_WAIT(0); }   // V(it) ready

        // ---- O += P V for both halves: shared B frags ----
        #pragma unroll
        for (int n = 0; n < 8; n++) {
            unsigned bh[8], bl[8];
            unsigned rowb = bufo + n * (8 * KROW) + laneoff;
            ldmat4(bh,     sb + AB_VH + rowb);
            ldmat4(bh + 4, sb + AB_VH + rowb + 64);
            ldmat4(bl,     sb + AB_VL + rowb);
            ldmat4(bl + 4, sb + AB_VL + rowb + 64);
            #pragma unroll
            for (int kg = 0; kg < 4; kg++) {
                MMAH(o0[n], ph0[kg], bh[kg * 2], bh[kg * 2 + 1]);
                MMAH(o0[n], pl0[kg], bh[kg * 2], bh[kg * 2 + 1]);
                MMAH(o0[n], ph0[kg], bl[kg * 2], bl[kg * 2 + 1]);
                MMAH(o1[n], ph1[kg], bh[kg * 2], bh[kg * 2 + 1]);
                MMAH(o1[n], pl1[kg], bh[kg * 2], bh[kg * 2 + 1]);
                MMAH(o1[n], ph1[kg], bl[kg * 2], bl[kg * 2 + 1]);
            }
        }
    }

    // ---- epilogue: normalize, store, fused absmax ----
    float i00 = __fdiv_rn(1.0f, l00), i08 = __fdiv_rn(1.0f, l08);
    float i10 = __fdiv_rn(1.0f, l10), i18 = __fdiv_rn(1.0f, l18);
    int qg = q0 + wid * 32 + g;
    float amax = 0.f;
    #pragma unroll
    for (int n = 0; n < 8; n++) {
        float a0 = o0[n][0] * i00, a1 = o0[n][1] * i00;
        float a2 = o0[n][2] * i08, a3 = o0[n][3] * i08;
        float a4 = o1[n][0] * i10, a5 = o1[n][1] * i10;
        float a6 = o1[n][2] * i18, a7 = o1[n][3] * i18;
        amax = fmaxf(amax, fmaxf(fmaxf(fabsf(a0), fabsf(a1)), fmaxf(fabsf(a2), fabsf(a3))));
        amax = fmaxf(amax, fmaxf(fmaxf(fabsf(a4), fabsf(a5)), fmaxf(fabsf(a6), fabsf(a7))));
        *(float2*)&g_attn[base + (size_t)qg * DIM + n * 8 + 2 * tig] = make_float2(a0, a1);
        *(float2*)&g_attn[base + (size_t)(qg + 8) * DIM + n * 8 + 2 * tig] = make_float2(a2, a3);
        *(float2*)&g_attn[base + (size_t)(qg + 16) * DIM + n * 8 + 2 * tig] = make_float2(a4, a5);
        *(float2*)&g_attn[base + (size_t)(qg + 24) * DIM + n * 8 + 2 * tig] = make_float2(a6, a7);
    }
    #pragma unroll
    for (int off = 16; off; off >>= 1) amax = fmaxf(amax, __shfl_xor_sync(0xffffffffu, amax, off));
    float* sred = (float*)(smc + AB_SRED);
    if (lane == 0) sred[wid] = amax;
    __syncthreads();
    if (tid == 0) {
        float mm = fmaxf(fmaxf(sred[0], sred[1]), fmaxf(sred[2], sred[3]));
        atomicMax(&g_absmax[5], __float_as_uint(mm));
    }
}

// ---------------- launch ----------------
extern "C" void kernel_launch(void* const* d_in, const int* in_sizes, int n_in,
                              void* d_out, int out_size) {
    const float* hidden = (const float*)d_in[0];
    const float* mask   = (const float*)d_in[1];
    const float* Wq = (const float*)d_in[2];
    const float* bq = (const float*)d_in[3];
    const float* Wk = (const float*)d_in[4];
    const float* bk = (const float*)d_in[5];
    const float* Wv = (const float*)d_in[6];
    const float* bv = (const float*)d_in[7];
    const float* Wo = (const float*)d_in[8];
    const float* bo = (const float*)d_in[9];
    float* out = (float*)d_out;

    cudaFuncSetAttribute(attn_k, cudaFuncAttributeMaxDynamicSharedMemorySize, AB_SMEM);
    const int GEMM_SMEM = 3 * STG_BYTES;

    absmax_all_k<<<dim3(256, 5), 256>>>(hidden, Wq, Wk, Wv, Wo);            // 1
    quant_all_k<<<dim3(256, 5), 256>>>(hidden, Wq, Wk, Wv, Wo);             // 2
    gemm_qkv_k<<<dim3(DIM / BN2, (BB * SS) / BM2, 3), 256, GEMM_SMEM>>>(bq, bk, bv); // 3
    attn_k<<<dim3(SS / 128, HH, BB), 128, AB_SMEM>>>(mask);                 // 4 <- ncu capture slot
    quant_attn_k<<<1024, 256>>>();                                          // 5
    gemm_o_k<<<dim3(DIM / BN2, (BB * SS) / BM2), 256, GEMM_SMEM>>>(bo, out); // 6
}

// round 13
// speedup vs baseline: 2.8568x; 1.0486x over previous
#include <cuda_runtime.h>
#include <cuda_bf16.h>
#include <cuda_fp16.h>

#define BB 2
#define SS 2048
#define DIM 1024
#define HH 16
#define HD 64
#define BSD (BB*SS*DIM)
#define DD  (DIM*DIM)

// ---------------- scratch ----------------
__device__ unsigned g_absmax[8];
__device__ float g_scales[8];
__device__ __align__(256) __nv_bfloat16 g_Xq[BSD];
__device__ __align__(256) __nv_bfloat16 g_Aq[BSD];
__device__ __align__(256) __nv_bfloat16 g_Wb[4][DD];
__device__ __align__(256) float g_Q[BSD];
__device__ __align__(256) __half g_Khi[BSD];   // [token][d] fp16 hi
__device__ __align__(256) __half g_Klo[BSD];   // [token][d] fp16 lo
__device__ __align__(256) __half g_VThi[BSD];  // [b,h][d][token] fp16 hi (transposed)
__device__ __align__(256) __half g_VTlo[BSD];
__device__ __align__(256) float g_attn[BSD];

// ---------------- helpers ----------------
__device__ __forceinline__ void cpasync16(unsigned saddr, const void* g) {
    asm volatile("cp.async.cg.shared.global [%0], [%1], 16;" :: "r"(saddr), "l"(g));
}
#define CP_COMMIT asm volatile("cp.async.commit_group;")
#define CP_WAIT(n) asm volatile("cp.async.wait_group %0;" :: "n"(n))

__device__ __forceinline__ void ldmat4(unsigned* r, unsigned addr) {
    asm volatile("ldmatrix.sync.aligned.m8n8.x4.shared.b16 {%0,%1,%2,%3},[%4];"
        : "=r"(r[0]), "=r"(r[1]), "=r"(r[2]), "=r"(r[3]) : "r"(addr));
}
__device__ __forceinline__ void mma16816(float* c, const unsigned* a, const unsigned* b) {
    asm volatile("mma.sync.aligned.m16n8k16.row.col.f32.bf16.bf16.f32 "
        "{%0,%1,%2,%3},{%4,%5,%6,%7},{%8,%9},{%0,%1,%2,%3};"
        : "+f"(c[0]), "+f"(c[1]), "+f"(c[2]), "+f"(c[3])
        : "r"(a[0]), "r"(a[1]), "r"(a[2]), "r"(a[3]), "r"(b[0]), "r"(b[1]));
}
// fp16 MMA, fp32 accumulate
#define MMAH(c, a, b0, b1) \
  asm volatile("mma.sync.aligned.m16n8k16.row.col.f32.f16.f16.f32 " \
    "{%0,%1,%2,%3},{%4,%5,%6,%7},{%8,%9},{%0,%1,%2,%3};" \
    : "+f"(c[0]), "+f"(c[1]), "+f"(c[2]), "+f"(c[3]) \
    : "r"(a[0]), "r"(a[1]), "r"(a[2]), "r"(a[3]), "r"(b0), "r"(b1))

// split (x,y) into packed fp16 hi/lo half2 pairs (Dekker)
__device__ __forceinline__ unsigned sp_split(float x, float y, unsigned& lo) {
    __half hx = __float2half_rn(x), hy = __float2half_rn(y);
    __half lx = __float2half_rn(x - __half2float(hx));
    __half ly = __float2half_rn(y - __half2float(hy));
    __half2 H = __halves2half2(hx, hy), L = __halves2half2(lx, ly);
    lo = *(unsigned*)&L;
    return *(unsigned*)&H;
}

__device__ __forceinline__ float max4(float4 v) {
    return fmaxf(fmaxf(fabsf(v.x), fabsf(v.y)), fmaxf(fabsf(v.z), fabsf(v.w)));
}

// ---------------- batched absmax (4-way ILP) ----------------
__global__ void absmax_all_k(const float* __restrict__ h,
                             const float* w0, const float* w1,
                             const float* w2, const float* w3) {
    int y = blockIdx.y;
    const float* x = y == 0 ? h : y == 1 ? w0 : y == 2 ? w1 : y == 3 ? w2 : w3;
    int n4 = (y == 0 ? BSD : DD) >> 2;
    const float4* x4 = (const float4*)x;
    float m = 0.f;
    int stride = gridDim.x * blockDim.x;
    for (int i = blockIdx.x * blockDim.x + threadIdx.x; i < n4; i += 4 * stride) {
        int i1 = i + stride, i2 = i + 2 * stride, i3 = i + 3 * stride;
        float m0 = max4(x4[i]);
        float m1 = (i1 < n4) ? max4(x4[i1]) : 0.f;
        float m2 = (i2 < n4) ? max4(x4[i2]) : 0.f;
        float m3 = (i3 < n4) ? max4(x4[i3]) : 0.f;
        m = fmaxf(m, fmaxf(fmaxf(m0, m1), fmaxf(m2, m3)));
    }
    #pragma unroll
    for (int o = 16; o; o >>= 1) m = fmaxf(m, __shfl_xor_sync(0xffffffffu, m, o));
    __shared__ float sm[8];
    if ((threadIdx.x & 31) == 0) sm[threadIdx.x >> 5] = m;
    __syncthreads();
    if (threadIdx.x < 32) {
        m = (threadIdx.x < 8u) ? sm[threadIdx.x] : 0.f;
        #pragma unroll
        for (int o = 4; o; o >>= 1) m = fmaxf(m, __shfl_xor_sync(0xffffffffu, m, o));
        if (threadIdx.x == 0) atomicMax(&g_absmax[y], __float_as_uint(m));
    }
}

// ---------------- batched quantize (4-way ILP) ----------------
__device__ __forceinline__ uint2 qpack(float4 v, float s) {
    __nv_bfloat162 lo = __floats2bfloat162_rn(rintf(__fdiv_rn(v.x, s)), rintf(__fdiv_rn(v.y, s)));
    __nv_bfloat162 hi = __floats2bfloat162_rn(rintf(__fdiv_rn(v.z, s)), rintf(__fdiv_rn(v.w, s)));
    uint2 p;
    p.x = *(unsigned*)&lo;
    p.y = *(unsigned*)&hi;
    return p;
}

__global__ void quant_all_k(const float* __restrict__ h,
                            const float* w0, const float* w1,
                            const float* w2, const float* w3) {
    int y = blockIdx.y;
    const float* x = y == 0 ? h : y == 1 ? w0 : y == 2 ? w1 : y == 3 ? w2 : w3;
    __nv_bfloat16* out = y == 0 ? g_Xq : g_Wb[y - 1];
    int n4 = (y == 0 ? BSD : DD) >> 2;
    float s = fmaxf(__fdiv_rn(__uint_as_float(g_absmax[y]), 127.0f), 1e-8f);
    if (blockIdx.x == 0 && threadIdx.x == 0) g_scales[y] = s;
    int stride = gridDim.x * blockDim.x;
    for (int i = blockIdx.x * blockDim.x + threadIdx.x; i < n4; i += 4 * stride) {
        int i1 = i + stride, i2 = i + 2 * stride, i3 = i + 3 * stride;
        float4 v0 = ((const float4*)x)[i];
        float4 v1, v2, v3;
        if (i1 < n4) v1 = ((const float4*)x)[i1];
        if (i2 < n4) v2 = ((const float4*)x)[i2];
        if (i3 < n4) v3 = ((const float4*)x)[i3];
        ((uint2*)out)[i] = qpack(v0, s);
        if (i1 < n4) ((uint2*)out)[i1] = qpack(v1, s);
        if (i2 < n4) ((uint2*)out)[i2] = qpack(v2, s);
        if (i3 < n4) ((uint2*)out)[i3] = qpack(v3, s);
    }
}

// ---------------- attn quantize (4-way ILP) ----------------
__global__ void quant_attn_k() {
    float s = fmaxf(__fdiv_rn(__uint_as_float(g_absmax[5]), 127.0f), 1e-8f);
    if (blockIdx.x == 0 && threadIdx.x == 0) g_scales[5] = s;
    int n4 = BSD >> 2;
    int stride = gridDim.x * blockDim.x;
    for (int i = blockIdx.x * blockDim.x + threadIdx.x; i < n4; i += 4 * stride) {
        int i1 = i + stride, i2 = i + 2 * stride, i3 = i + 3 * stride;
        float4 v0 = ((const float4*)g_attn)[i];
        float4 v1, v2, v3;
        if (i1 < n4) v1 = ((const float4*)g_attn)[i1];
        if (i2 < n4) v2 = ((const float4*)g_attn)[i2];
        if (i3 < n4) v3 = ((const float4*)g_attn)[i3];
        ((uint2*)g_Aq)[i] = qpack(v0, s);
        if (i1 < n4) ((uint2*)g_Aq)[i1] = qpack(v1, s);
        if (i2 < n4) ((uint2*)g_Aq)[i2] = qpack(v2, s);
        if (i3 < n4) ((uint2*)g_Aq)[i3] = qpack(v3, s);
    }
}

// ================= pipelined bf16 GEMM, 128x128 tiles =================
#define BM2 128
#define BN2 128
#define BK2 32
#define PKB 80
#define STG_A (BM2 * PKB)                 /* 10240 */
#define STG_BYTES ((BM2 + BN2) * PKB)     /* 20480 */
#define KTILES (DIM / BK2)                /* 32 */

__device__ __forceinline__ void gemm_body(const __nv_bfloat16* __restrict__ A,
                                          const __nv_bfloat16* __restrict__ B,
                                          const float* __restrict__ bias,
                                          float* __restrict__ cext, int c_sel,
                                          float scale, char* sm2) {
    const int rb = blockIdx.y * BM2, cb = blockIdx.x * BN2;
    const int tid = threadIdx.x, wid = tid >> 5, lane = tid & 31;
    const unsigned sbase = (unsigned)__cvta_generic_to_shared(sm2);

    const int wm = wid & 1, wn = wid >> 1;    // 2 (m) x 4 (n) warps; warp = 64 rows x 32 cols
    const int a_row = wm * 64 + (lane & 7) + ((lane >> 3) & 1) * 8;   // + mt*16
    const int a_koff = (lane >> 4) * 8;
    const int b_row = wn * 32 + (lane & 7) + (lane >> 4) * 8;         // + 16 for 2nd ldmat
    const int b_koff = ((lane >> 3) & 1) * 8;

    float c[4][4][4];
    #pragma unroll
    for (int mt = 0; mt < 4; mt++)
        #pragma unroll
        for (int nt = 0; nt < 4; nt++)
            #pragma unroll
            for (int e = 0; e < 4; e++) c[mt][nt][e] = 0.f;

    auto issue = [&](int ki) {
        int kt = ki * BK2;
        unsigned s = sbase + (ki % 3) * STG_BYTES;
        #pragma unroll
        for (int r2 = 0; r2 < 2; r2++) {
            int idx = tid + r2 * 256;
            int row = idx >> 2, ch = idx & 3;
            cpasync16(s + row * PKB + ch * 16, A + (size_t)(rb + row) * DIM + kt + ch * 8);
        }
        #pragma unroll
        for (int r2 = 0; r2 < 2; r2++) {
            int idx = tid + r2 * 256;
            int row = idx >> 2, ch = idx & 3;
            cpasync16(s + STG_A + row * PKB + ch * 16, B + (size_t)(cb + row) * DIM + kt + ch * 8);
        }
        CP_COMMIT;
    };

    issue(0);
    issue(1);

    for (int i = 0; i < KTILES; i++) {
        if (i + 1 < KTILES) { CP_WAIT(1); } else { CP_WAIT(0); }
        __syncthreads();
        if (i + 2 < KTILES) issue(i + 2);
        unsigned s = sbase + (i % 3) * STG_BYTES;
        #pragma unroll
        for (int ks = 0; ks < BK2; ks += 16) {
            unsigned af[4][4], bfA[4], bfB[4];
            #pragma unroll
            for (int mt = 0; mt < 4; mt++)
                ldmat4(af[mt], s + (a_row + mt * 16) * PKB + (ks + a_koff) * 2);
            ldmat4(bfA, s + STG_A + b_row * PKB + (ks + b_koff) * 2);
            ldmat4(bfB, s + STG_A + (b_row + 16) * PKB + (ks + b_koff) * 2);
            #pragma unroll
            for (int mt = 0; mt < 4; mt++)
                #pragma unroll
                for (int nt = 0; nt < 4; nt++)
                    mma16816(c[mt][nt], af[mt], (nt < 2) ? &bfA[nt * 2] : &bfB[(nt - 2) * 2]);
        }
        __syncthreads();
    }

    const int g = lane >> 2, tig = lane & 3;
    #pragma unroll
    for (int mt = 0; mt < 4; mt++) {
        #pragma unroll
        for (int nt = 0; nt < 4; nt++) {
            int col = cb + wn * 32 + nt * 8 + 2 * tig;
            float2 bv = *(const float2*)&bias[col];
            #pragma unroll
            for (int half = 0; half < 2; half++) {
                int row = rb + wm * 64 + mt * 16 + g + half * 8;
                float x = c[mt][nt][half * 2]     * scale + bv.x;
                float y = c[mt][nt][half * 2 + 1] * scale + bv.y;
                size_t off = (size_t)row * DIM + col;
                if (c_sel == 0) {
                    *(float2*)&g_Q[off] = make_float2(x, y);
                } else if (c_sel == 1) {
                    unsigned lo, hi = sp_split(x, y, lo);
                    *(unsigned*)&g_Khi[off] = hi;
                    *(unsigned*)&g_Klo[off] = lo;
                } else if (c_sel == 2) {
                    __half hx = __float2half_rn(x), hy = __float2half_rn(y);
                    __half lx = __float2half_rn(x - __half2float(hx));
                    __half ly = __float2half_rn(y - __half2float(hy));
                    int brow = row >> 11, tok = row & (SS - 1);
                    int hh = col >> 6, dd = col & 63;
                    size_t offT = ((size_t)((brow * HH + hh) * HD + dd)) * SS + tok;
                    g_VThi[offT] = hx;      g_VTlo[offT] = lx;
                    g_VThi[offT + SS] = hy; g_VTlo[offT + SS] = ly;
                } else {
                    *(float2*)&cext[off] = make_float2(x, y);
                }
            }
        }
    }
}

__global__ void __launch_bounds__(256, 2) gemm_qkv_k(const float* __restrict__ bq,
                                                     const float* __restrict__ bk,
                                                     const float* __restrict__ bv) {
    extern __shared__ char sm2[];
    int z = blockIdx.z;
    const float* bias = z == 0 ? bq : z == 1 ? bk : bv;
    float scale = g_scales[0] * g_scales[1 + z];
    gemm_body(g_Xq, g_Wb[z], bias, nullptr, z, scale, sm2);
}

__global__ void __launch_bounds__(256, 2) gemm_o_k(const float* __restrict__ bo,
                                                   float* __restrict__ out) {
    extern __shared__ char sm2[];
    float scale = g_scales[5] * g_scales[4];
    gemm_body(g_Aq, g_Wb[3], bo, out, 3, scale, sm2);
}

// ================= fp16 3-term flash attention, 32 q-rows/warp (unchanged R12) ======
#define KROW 144
#define PLANE (64 * KROW)

#define AB_KH 0
#define AB_KL (2 * PLANE)
#define AB_VH (4 * PLANE)
#define AB_VL (6 * PLANE)
#define AB_MS (8 * PLANE)
#define AB_SRED (AB_MS + 512)
#define AB_SMEM (AB_SRED + 32)

__global__ void __launch_bounds__(128, 2) attn_k(const float* __restrict__ mask) {
    extern __shared__ char smc[];
    const unsigned sb = (unsigned)__cvta_generic_to_shared(smc);

    const int b = blockIdx.z, h = blockIdx.y;
    const int q0 = blockIdx.x * 128;
    const int tid = threadIdx.x;
    const int wid = tid >> 5, lane = tid & 31;
    const int g = lane >> 2, tig = lane & 3;
    const size_t base = (size_t)b * SS * DIM + (size_t)h * HD;
    const size_t baseT = (size_t)(b * HH + h) * HD * SS;

    const unsigned laneoff = (lane & 7) * KROW + (lane >> 3) * 16;

    unsigned qh0[4][4], ql0[4][4], qh1[4][4], ql1[4][4];
    {
        const float* Qa = &g_Q[base + (size_t)(q0 + wid * 32 + g) * DIM];
        const float* Qb = Qa + 16 * DIM;
        #pragma unroll
        for (int kg = 0; kg < 4; kg++) {
            float2 v0 = *(const float2*)&Qa[kg * 16 + 2 * tig];
            float2 v1 = *(const float2*)&Qa[8 * DIM + kg * 16 + 2 * tig];
            float2 v2 = *(const float2*)&Qa[kg * 16 + 2 * tig + 8];
            float2 v3 = *(const float2*)&Qa[8 * DIM + kg * 16 + 2 * tig + 8];
            qh0[kg][0] = sp_split(v0.x * 0.125f, v0.y * 0.125f, ql0[kg][0]);
            qh0[kg][1] = sp_split(v1.x * 0.125f, v1.y * 0.125f, ql0[kg][1]);
            qh0[kg][2] = sp_split(v2.x * 0.125f, v2.y * 0.125f, ql0[kg][2]);
            qh0[kg][3] = sp_split(v3.x * 0.125f, v3.y * 0.125f, ql0[kg][3]);
            v0 = *(const float2*)&Qb[kg * 16 + 2 * tig];
            v1 = *(const float2*)&Qb[8 * DIM + kg * 16 + 2 * tig];
            v2 = *(const float2*)&Qb[kg * 16 + 2 * tig + 8];
            v3 = *(const float2*)&Qb[8 * DIM + kg * 16 + 2 * tig + 8];
            qh1[kg][0] = sp_split(v0.x * 0.125f, v0.y * 0.125f, ql1[kg][0]);
            qh1[kg][1] = sp_split(v1.x * 0.125f, v1.y * 0.125f, ql1[kg][1]);
            qh1[kg][2] = sp_split(v2.x * 0.125f, v2.y * 0.125f, ql1[kg][2]);
            qh1[kg][3] = sp_split(v3.x * 0.125f, v3.y * 0.125f, ql1[kg][3]);
        }
    }

    auto issue_K = [&](int kt, int buf) {
        const char* gKh = (const char*)&g_Khi[base + (size_t)kt * DIM];
        const char* gKl = (const char*)&g_Klo[base + (size_t)kt * DIM];
        unsigned o = buf * PLANE;
        #pragma unroll
        for (int c = 0; c < 4; c++) {
            int idx = tid + c * 128;
            int r = idx >> 3, ch = idx & 7;
            unsigned so = o + r * KROW + ch * 16;
            cpasync16(sb + AB_KH + so, gKh + (size_t)r * (DIM * 2) + ch * 16);
            cpasync16(sb + AB_KL + so, gKl + (size_t)r * (DIM * 2) + ch * 16);
        }
        if (tid < 16)
            cpasync16(sb + AB_MS + buf * 256 + tid * 16,
                      (const char*)&mask[(size_t)b * SS + kt] + tid * 16);
        CP_COMMIT;
    };
    auto issue_V = [&](int kt, int buf) {
        const char* gVh = (const char*)g_VThi + 2 * (baseT + kt);
        const char* gVl = (const char*)g_VTlo + 2 * (baseT + kt);
        unsigned o = buf * PLANE;
        #pragma unroll
        for (int c = 0; c < 4; c++) {
            int idx = tid + c * 128;
            int r = idx >> 3, ch = idx & 7;
            unsigned so = o + r * KROW + ch * 16;
            cpasync16(sb + AB_VH + so, gVh + (size_t)r * (SS * 2) + ch * 16);
            cpasync16(sb + AB_VL + so, gVl + (size_t)r * (SS * 2) + ch * 16);
        }
        CP_COMMIT;
    };

    issue_K(0, 0);
    issue_V(0, 0);

    float m00 = -1e30f, m08 = -1e30f, m10 = -1e30f, m18 = -1e30f;
    float l00 = 0.f, l08 = 0.f, l10 = 0.f, l18 = 0.f;
    float o0[8][4], o1[8][4];
    #pragma unroll
    for (int n = 0; n < 8; n++)
        #pragma unroll
        for (int e = 0; e < 4; e++) { o0[n][e] = 0.f; o1[n][e] = 0.f; }

    for (int it = 0; it < SS / 64; it++) {
        const int cur = it & 1;
        __syncthreads();
        if (it + 1 < SS / 64) {
            issue_K((it + 1) * 64, 1 - cur);
            issue_V((it + 1) * 64, 1 - cur);
            CP_WAIT(3);
        } else {
            CP_WAIT(1);
        }

        const unsigned bufo = cur * PLANE;
        const float* Mc = (const float*)(smc + AB_MS + cur * 256);

        float s0[8][4], s1[8][4];
        #pragma unroll
        for (int n = 0; n < 8; n++)
            #pragma unroll
            for (int e = 0; e < 4; e++) { s0[n][e] = 0.f; s1[n][e] = 0.f; }

        #pragma unroll
        for (int n = 0; n < 8; n++) {
            unsigned bh[8], bl[8];
            unsigned rowb = bufo + n * (8 * KROW) + laneoff;
            ldmat4(bh,     sb + AB_KH + rowb);
            ldmat4(bh + 4, sb + AB_KH + rowb + 64);
            ldmat4(bl,     sb + AB_KL + rowb);
            ldmat4(bl + 4, sb + AB_KL + rowb + 64);
            #pragma unroll
            for (int kg = 0; kg < 4; kg++) {
                MMAH(s0[n], qh0[kg], bh[kg * 2], bh[kg * 2 + 1]);
                MMAH(s0[n], ql0[kg], bh[kg * 2], bh[kg * 2 + 1]);
                MMAH(s0[n], qh0[kg], bl[kg * 2], bl[kg * 2 + 1]);
                MMAH(s1[n], qh1[kg], bh[kg * 2], bh[kg * 2 + 1]);
                MMAH(s1[n], ql1[kg], bh[kg * 2], bh[kg * 2 + 1]);
                MMAH(s1[n], qh1[kg], bl[kg * 2], bl[kg * 2 + 1]);
            }
        }

        float mx00 = -1e30f, mx08 = -1e30f, mx10 = -1e30f, mx18 = -1e30f;
        #pragma unroll
        for (int n = 0; n < 8; n++) {
            float2 mm = *(const float2*)&Mc[n * 8 + 2 * tig];
            float bx = mm.x * 10000.0f - 10000.0f;
            float by = mm.y * 10000.0f - 10000.0f;
            s0[n][0] += bx; s0[n][1] += by; s0[n][2] += bx; s0[n][3] += by;
            s1[n][0] += bx; s1[n][1] += by; s1[n][2] += bx; s1[n][3] += by;
            mx00 = fmaxf(mx00, fmaxf(s0[n][0], s0[n][1]));
            mx08 = fmaxf(mx08, fmaxf(s0[n][2], s0[n][3]));
            mx10 = fmaxf(mx10, fmaxf(s1[n][0], s1[n][1]));
            mx18 = fmaxf(mx18, fmaxf(s1[n][2], s1[n][3]));
        }
        #pragma unroll
        for (int o = 1; o < 4; o <<= 1) {
            mx00 = fmaxf(mx00, __shfl_xor_sync(0xffffffffu, mx00, o));
            mx08 = fmaxf(mx08, __shfl_xor_sync(0xffffffffu, mx08, o));
            mx10 = fmaxf(mx10, __shfl_xor_sync(0xffffffffu, mx10, o));
            mx18 = fmaxf(mx18, __shfl_xor_sync(0xffffffffu, mx18, o));
        }
        float mn00 = fmaxf(m00, mx00), mn08 = fmaxf(m08, mx08);
        float mn10 = fmaxf(m10, mx10), mn18 = fmaxf(m18, mx18);
        float c00 = __expf(m00 - mn00), c08 = __expf(m08 - mn08);
        float c10 = __expf(m10 - mn10), c18 = __expf(m18 - mn18);
        float su00 = 0.f, su08 = 0.f, su10 = 0.f, su18 = 0.f;
        #pragma unroll
        for (int n = 0; n < 8; n++) {
            s0[n][0] = __expf(s0[n][0] - mn00); su00 += s0[n][0];
            s0[n][1] = __expf(s0[n][1] - mn00); su00 += s0[n][1];
            s0[n][2] = __expf(s0[n][2] - mn08); su08 += s0[n][2];
            s0[n][3] = __expf(s0[n][3] - mn08); su08 += s0[n][3];
            s1[n][0] = __expf(s1[n][0] - mn10); su10 += s1[n][0];
            s1[n][1] = __expf(s1[n][1] - mn10); su10 += s1[n][1];
            s1[n][2] = __expf(s1[n][2] - mn18); su18 += s1[n][2];
            s1[n][3] = __expf(s1[n][3] - mn18); su18 += s1[n][3];
        }
        #pragma unroll
        for (int o = 1; o < 4; o <<= 1) {
            su00 += __shfl_xor_sync(0xffffffffu, su00, o);
            su08 += __shfl_xor_sync(0xffffffffu, su08, o);
            su10 += __shfl_xor_sync(0xffffffffu, su10, o);
            su18 += __shfl_xor_sync(0xffffffffu, su18, o);
        }
        l00 = l00 * c00 + su00; l08 = l08 * c08 + su08;
        l10 = l10 * c10 + su10; l18 = l18 * c18 + su18;
        m00 = mn00; m08 = mn08; m10 = mn10; m18 = mn18;

        #pragma unroll
        for (int n = 0; n < 8; n++) {
            o0[n][0] *= c00; o0[n][1] *= c00; o0[n][2] *= c08; o0[n][3] *= c08;
            o1[n][0] *= c10; o1[n][1] *= c10; o1[n][2] *= c18; o1[n][3] *= c18;
        }

        unsigned ph0[4][4], pl0[4][4], ph1[4][4], pl1[4][4];
        #pragma unroll
        for (int kg = 0; kg < 4; kg++) {
            ph0[kg][0] = sp_split(s0[2 * kg][0],     s0[2 * kg][1],     pl0[kg][0]);
            ph0[kg][1] = sp_split(s0[2 * kg][2],     s0[2 * kg][3],     pl0[kg][1]);
            ph0[kg][2] = sp_split(s0[2 * kg + 1][0], s0[2 * kg + 1][1], pl0[kg][2]);
            ph0[kg][3] = sp_split(s0[2 * kg + 1][2], s0[2 * kg + 1][3], pl0[kg][3]);
            ph1[kg][0] = sp_split(s1[2 * kg][0],     s1[2 * kg][1],     pl1[kg][0]);
            ph1[kg][1] = sp_split(s1[2 * kg][2],     s1[2 * kg][3],     pl1[kg][1]);
            ph1[kg][2] = sp_split(s1[2 * kg + 1][0], s1[2 * kg + 1][1], pl1[kg][2]);
            ph1[kg][3] = sp_split(s1[2 * kg + 1][2], s1[2 * kg + 1][3], pl1[kg][3]);
        }

        if (it + 1 < SS / 64) { CP_WAIT(2); } else { CP_WAIT(0); }

        #pragma unroll
        for (int n = 0; n < 8; n++) {
            unsigned bh[8], bl[8];
            unsigned rowb = bufo + n * (8 * KROW) + laneoff;
            ldmat4(bh,     sb + AB_VH + rowb);
            ldmat4(bh + 4, sb + AB_VH + rowb + 64);
            ldmat4(bl,     sb + AB_VL + rowb);
            ldmat4(bl + 4, sb + AB_VL + rowb + 64);
            #pragma unroll
            for (int kg = 0; kg < 4; kg++) {
                MMAH(o0[n], ph0[kg], bh[kg * 2], bh[kg * 2 + 1]);
                MMAH(o0[n], pl0[kg], bh[kg * 2], bh[kg * 2 + 1]);
                MMAH(o0[n], ph0[kg], bl[kg * 2], bl[kg * 2 + 1]);
                MMAH(o1[n], ph1[kg], bh[kg * 2], bh[kg * 2 + 1]);
                MMAH(o1[n], pl1[kg], bh[kg * 2], bh[kg * 2 + 1]);
                MMAH(o1[n], ph1[kg], bl[kg * 2], bl[kg * 2 + 1]);
            }
        }
    }

    float i00 = __fdiv_rn(1.0f, l00), i08 = __fdiv_rn(1.0f, l08);
    float i10 = __fdiv_rn(1.0f, l10), i18 = __fdiv_rn(1.0f, l18);
    int qg = q0 + wid * 32 + g;
    float amax = 0.f;
    #pragma unroll
    for (int n = 0; n < 8; n++) {
        float a0 = o0[n][0] * i00, a1 = o0[n][1] * i00;
        float a2 = o0[n][2] * i08, a3 = o0[n][3] * i08;
        float a4 = o1[n][0] * i10, a5 = o1[n][1] * i10;
        float a6 = o1[n][2] * i18, a7 = o1[n][3] * i18;
        amax = fmaxf(amax, fmaxf(fmaxf(fabsf(a0), fabsf(a1)), fmaxf(fabsf(a2), fabsf(a3))));
        amax = fmaxf(amax, fmaxf(fmaxf(fabsf(a4), fabsf(a5)), fmaxf(fabsf(a6), fabsf(a7))));
        *(float2*)&g_attn[base + (size_t)qg * DIM + n * 8 + 2 * tig] = make_float2(a0, a1);
        *(float2*)&g_attn[base + (size_t)(qg + 8) * DIM + n * 8 + 2 * tig] = make_float2(a2, a3);
        *(float2*)&g_attn[base + (size_t)(qg + 16) * DIM + n * 8 + 2 * tig] = make_float2(a4, a5);
        *(float2*)&g_attn[base + (size_t)(qg + 24) * DIM + n * 8 + 2 * tig] = make_float2(a6, a7);
    }
    #pragma unroll
    for (int off = 16; off; off >>= 1) amax = fmaxf(amax, __shfl_xor_sync(0xffffffffu, amax, off));
    float* sred = (float*)(smc + AB_SRED);
    if (lane == 0) sred[wid] = amax;
    __syncthreads();
    if (tid == 0) {
        float mm = fmaxf(fmaxf(sred[0], sred[1]), fmaxf(sred[2], sred[3]));
        atomicMax(&g_absmax[5], __float_as_uint(mm));
    }
}

// ---------------- launch ----------------
extern "C" void kernel_launch(void* const* d_in, const int* in_sizes, int n_in,
                              void* d_out, int out_size) {
    const float* hidden = (const float*)d_in[0];
    const float* mask   = (const float*)d_in[1];
    const float* Wq = (const float*)d_in[2];
    const float* bq = (const float*)d_in[3];
    const float* Wk = (const float*)d_in[4];
    const float* bk = (const float*)d_in[5];
    const float* Wv = (const float*)d_in[6];
    const float* bv = (const float*)d_in[7];
    const float* Wo = (const float*)d_in[8];
    const float* bo = (const float*)d_in[9];
    float* out = (float*)d_out;

    cudaFuncSetAttribute(attn_k, cudaFuncAttributeMaxDynamicSharedMemorySize, AB_SMEM);
    const int GEMM_SMEM = 3 * STG_BYTES;   // 61440
    cudaFuncSetAttribute(gemm_qkv_k, cudaFuncAttributeMaxDynamicSharedMemorySize, GEMM_SMEM);
    cudaFuncSetAttribute(gemm_o_k, cudaFuncAttributeMaxDynamicSharedMemorySize, GEMM_SMEM);

    absmax_all_k<<<dim3(256, 5), 256>>>(hidden, Wq, Wk, Wv, Wo);            // 1
    quant_all_k<<<dim3(256, 5), 256>>>(hidden, Wq, Wk, Wv, Wo);             // 2
    gemm_qkv_k<<<dim3(DIM / BN2, (BB * SS) / BM2, 3), 256, GEMM_SMEM>>>(bq, bk, bv); // 3
    attn_k<<<dim3(SS / 128, HH, BB), 128, AB_SMEM>>>(mask);                 // 4 <- ncu capture slot
    quant_attn_k<<<512, 256>>>();                                           // 5
    gemm_o_k<<<dim3(DIM / BN2, (BB * SS) / BM2), 256, GEMM_SMEM>>>(bo, out); // 6
}